// round 14
// baseline (speedup 1.0000x reference)
#include <cuda_runtime.h>
#include <cuda_bf16.h>
#include <cstdint>

// Problem constants
#define Sx 512
#define Bx 64
#define Ex 512
#define Hx 768
#define G4x 3072
#define SBx 32768      // Sx*Bx
#define KX 1536        // tripled-K for compensated bf16 GEMM (B side)
#define AX 1024        // A side: [Ah | Al] only
#define NCTA 144       // fwd persistent grid (24 nblk x 6 kc)
#define NTHR 36864     // NCTA*256
#define NUNIT 24576    // Bx*Hx/2 gate units (float2)
#define PARTSZ ((size_t)6 * Bx * G4x)  // one partials buffer

// ---------------- scratch (device globals: allocation-guard-safe) -------------
__device__ __nv_bfloat16 g_ax[(size_t)SBx * AX];    // 67 MB   [Ah | Al]
__device__ __nv_bfloat16 g_bxf[(size_t)G4x * KX];   // 9.4 MB  [Bh ; Bh ; Bl] fwd
__device__ __nv_bfloat16 g_bxb[(size_t)G4x * KX];   // 9.4 MB  [Bh ; Bh ; Bl] bwd
__device__ float g_xf[(size_t)SBx * G4x];    // 402 MB  emb@Wi_f + bi_f     [SB,4H]
__device__ float g_gb[(size_t)SBx * G4x];    // 402 MB  emb@Wi_b + bi_b     [SB,4H]
__device__ float g_hsf[(size_t)SBx * Hx];    // 100 MB  forward hiddens     [S,B,H]
__device__ float g_hsb[(size_t)SBx * Hx];    // 100 MB  backward hiddens    [S,B,H]
__device__ float g_part[2 * PARTSZ];         // 9.4 MB  double-buffered partials
__device__ uint32_t g_hhi[NUNIT];            // current hidden hi (bf16x2)
__device__ uint32_t g_hlo[NUNIT];            // current hidden lo (bf16x2)
__device__ unsigned int g_flags[NCTA];       // global barrier per-CTA gen
__device__ unsigned int g_gflags[NCTA];      // group barrier per-CTA gen
__device__ unsigned int g_bar_gen;           // global broadcast generation

// ---------------- f32x2 helpers (for step_gemm one-shot) -----------------------
__device__ __forceinline__ void fma2(unsigned long long& d, unsigned long long a,
                                     unsigned long long b) {
    asm("fma.rn.f32x2 %0, %1, %2, %0;" : "+l"(d) : "l"(a), "l"(b));
}
__device__ __forceinline__ unsigned long long pack2(float x) {
    unsigned long long r;
    asm("mov.b64 %0, {%1, %1};" : "=l"(r) : "f"(x));
    return r;
}
__device__ __forceinline__ float2 unpack2(unsigned long long v) {
    float2 f;
    asm("mov.b64 {%0, %1}, %2;" : "=f"(f.x), "=f"(f.y) : "l"(v));
    return f;
}

// ---------------- fast transcendentals (MUFU, rel err ~3e-7) -------------------
__device__ __forceinline__ float fsigm(float x) {
    float t, r;
    asm("ex2.approx.f32 %0, %1;" : "=f"(t) : "f"(-1.4426950408889634f * x));
    asm("rcp.approx.f32 %0, %1;" : "=f"(r) : "f"(1.0f + t));
    return r;
}
__device__ __forceinline__ float ftanh(float x) {
    return fmaf(2.0f, fsigm(2.0f * x), -1.0f);
}

// ---------------- misc helpers --------------------------------------------------
__device__ __forceinline__ uint32_t smem_u32(const void* p) {
    uint32_t a;
    asm("{ .reg .u64 t; cvta.to.shared.u64 t, %1; cvt.u32.u64 %0, t; }"
        : "=r"(a) : "l"(p));
    return a;
}
__device__ __forceinline__ void st_rel(unsigned int* p, unsigned int v) {
    asm volatile("st.release.gpu.global.u32 [%0], %1;" :: "l"(p), "r"(v) : "memory");
}
__device__ __forceinline__ unsigned int ld_acq(const unsigned int* p) {
    unsigned int v;
    asm volatile("ld.acquire.gpu.global.u32 %0, [%1];" : "=r"(v) : "l"(p) : "memory");
    return v;
}

// global grid barrier: per-CTA flag release; CTA0 aggregates and broadcasts.
__device__ __forceinline__ void gsync(unsigned int& gen) {
    __syncthreads();
    gen++;
    if (threadIdx.x == 0) {
        st_rel(&g_flags[blockIdx.x], gen);  // release orders prior writes
    }
    if (blockIdx.x == 0) {
        if (threadIdx.x < NCTA) {
            while ((int)(ld_acq(&g_flags[threadIdx.x]) - gen) < 0) {}
        }
        __syncthreads();
        if (threadIdx.x == 0) st_rel(&g_bar_gen, gen);
    } else {
        if (threadIdx.x == 0) {
            while ((int)(ld_acq(&g_bar_gen) - gen) < 0) {}
        }
    }
    __syncthreads();
}

// group barrier: all-to-all among the 24 CTAs of group kc (bids kc*24..kc*24+23).
// 1-hop: each CTA releases its flag; threads 0..23 poll the group's flags.
__device__ __forceinline__ void gsync_group(unsigned int& ggen, int kc) {
    __syncthreads();
    ggen++;
    if (threadIdx.x == 0) {
        st_rel(&g_gflags[blockIdx.x], ggen);  // release orders prior writes
    }
    if (threadIdx.x < 24) {
        const unsigned int* f = &g_gflags[kc * 24 + threadIdx.x];
        while ((int)(ld_acq(f) - ggen) < 0) {}
    }
    __syncthreads();
}

// ---------------- mma.sync / ldmatrix / cp.async macros -------------------------
#define LDSM4(r, addr) \
    asm volatile("ldmatrix.sync.aligned.m8n8.x4.shared.b16 {%0,%1,%2,%3}, [%4];" \
                 : "=r"((r)[0]), "=r"((r)[1]), "=r"((r)[2]), "=r"((r)[3]) \
                 : "r"(addr))
#define MMA16816(c, a, b0v, b1v) \
    asm volatile("mma.sync.aligned.m16n8k16.row.col.f32.bf16.bf16.f32 " \
                 "{%0,%1,%2,%3}, {%4,%5,%6,%7}, {%8,%9}, {%0,%1,%2,%3};" \
                 : "+f"((c)[0]), "+f"((c)[1]), "+f"((c)[2]), "+f"((c)[3]) \
                 : "r"((a)[0]), "r"((a)[1]), "r"((a)[2]), "r"((a)[3]), \
                   "r"(b0v), "r"(b1v))
__device__ __forceinline__ void cp16(uint32_t dst, const void* src) {
    asm volatile("cp.async.cg.shared.global [%0], [%1], 16;"
                 :: "r"(dst), "l"(src));
}
#define CP_COMMIT() asm volatile("cp.async.commit_group;" ::: "memory")
#define CP_WAIT(n) asm volatile("cp.async.wait_group %0;" :: "n"(n) : "memory")
__device__ __forceinline__ void sst16(uint32_t addr, unsigned short v) {
    asm volatile("st.shared.b16 [%0], %1;" :: "r"(addr), "h"(v));
}

// ---------------- 1. embedding gather + compensated layout ---------------------
__device__ __forceinline__ uint32_t packbf2(float a, float b) {
    __nv_bfloat162 t = __floats2bfloat162_rn(a, b);
    return *(uint32_t*)&t;
}
__global__ void embed_split_kernel(const int* __restrict__ tokens,
                                   const float* __restrict__ embedding) {
    int idx = blockIdx.x * blockDim.x + threadIdx.x;  // over SB * 64 (8 elems each)
    int e8 = idx & 63;
    int sb = idx >> 6;
    int tok = tokens[sb];
    const float4* src = (const float4*)(embedding + (size_t)tok * Ex + e8 * 8);
    float4 v0 = src[0], v1 = src[1];
    float hv[8], lo[8];
    float in[8] = {v0.x, v0.y, v0.z, v0.w, v1.x, v1.y, v1.z, v1.w};
#pragma unroll
    for (int i = 0; i < 8; ++i) {
        hv[i] = __bfloat162float(__float2bfloat16_rn(in[i]));
        lo[i] = in[i] - hv[i];
    }
    uint4 ph, pl;
    ph.x = packbf2(in[0], in[1]); ph.y = packbf2(in[2], in[3]);
    ph.z = packbf2(in[4], in[5]); ph.w = packbf2(in[6], in[7]);
    pl.x = packbf2(lo[0], lo[1]); pl.y = packbf2(lo[2], lo[3]);
    pl.z = packbf2(lo[4], lo[5]); pl.w = packbf2(lo[6], lo[7]);
    size_t off = (size_t)sb * AX + e8 * 8;
    *(uint4*)(g_ax + off) = ph;
    *(uint4*)(g_ax + off + 512) = pl;
}

// ---------------- 1b. W transpose + compensated layout --------------------------
__global__ void wsplit_kernel(const float* __restrict__ W, int which) {
    __shared__ float tile[32][33];
    __nv_bfloat16* dst = which ? g_bxb : g_bxf;
    const int kb = blockIdx.x;  // 16
    const int nb = blockIdx.y;  // 96
    const int t = threadIdx.x;
    const int c = t & 31;
    const int r0 = t >> 5;  // 0..7
#pragma unroll
    for (int q = 0; q < 4; ++q) {
        int r = r0 + 8 * q;
        tile[r][c] = W[(size_t)(kb * 32 + r) * G4x + nb * 32 + c];
    }
    __syncthreads();
#pragma unroll
    for (int q = 0; q < 4; ++q) {
        int i = r0 + 8 * q;            // n within tile
        float v = tile[c][i];          // W[kb*32+c][nb*32+i]
        __nv_bfloat16 hb = __float2bfloat16_rn(v);
        float hvf = __bfloat162float(hb);
        size_t off = (size_t)(nb * 32 + i) * KX + kb * 32 + c;
        dst[off] = hb;
        dst[off + 512] = hb;
        dst[off + 1024] = __float2bfloat16_rn(v - hvf);
    }
}

// ---------------- 2. warp-MMA input GEMM (uniform bf16, K=1536, 3-stage) --------
#define TCW_STAGE 24576                 // A 8KB + B 16KB
#define TCW_SMEM (3 * TCW_STAGE)        // 72 KB

__device__ __forceinline__ void load_tileA64(const __nv_bfloat16* __restrict__ g,
                                             uint32_t sbase, int blk, int t) {
    int aoff = (blk < 16 ? blk : blk - 16) * 128;  // byte offset in 2048B row
#pragma unroll
    for (int q = 0; q < 4; ++q) {
        int idx = t + 128 * q;         // < 512 : 64 rows x 8 chunks
        int r = idx >> 3, c = idx & 7;
        const char* src = (const char*)g + (size_t)r * (AX * 2) + aoff + c * 16;
        uint32_t dst = sbase + r * 128 + ((c ^ (r & 7)) << 4);
        cp16(dst, src);
    }
}
__device__ __forceinline__ void load_tileB128(const __nv_bfloat16* __restrict__ g,
                                              uint32_t sbase, int blk, int t) {
#pragma unroll
    for (int q = 0; q < 8; ++q) {
        int idx = t + 128 * q;         // < 1024 : 128 rows x 8 chunks
        int r = idx >> 3, c = idx & 7;
        const char* src = (const char*)g + (size_t)r * (KX * 2) + blk * 128 + c * 16;
        uint32_t dst = sbase + r * 128 + ((c ^ (r & 7)) << 4);
        cp16(dst, src);
    }
}

__global__ __launch_bounds__(128, 2)
void tcw_gemm(const float* __restrict__ bias, int which) {
    extern __shared__ char smraw[];
    uint32_t smb = smem_u32(smraw);
    const int t = threadIdx.x;
    const int l = t & 31;
    const int wid = t >> 5;            // 0..3
    const int nblk = blockIdx.x;       // 24
    const int mblk = blockIdx.y;       // 512 (rows of 64)

    const __nv_bfloat16* Ag = g_ax + (size_t)mblk * 64 * AX;
    const __nv_bfloat16* Bg = (which ? g_bxb : g_bxf) + (size_t)nblk * 128 * KX;
    float* out = which ? g_gb : g_xf;

    float acc[2][8][4];
#pragma unroll
    for (int i = 0; i < 2; ++i)
#pragma unroll
        for (int j = 0; j < 8; ++j)
#pragma unroll
            for (int q = 0; q < 4; ++q) acc[i][j][q] = 0.0f;

    const int warp_m0 = (wid & 1) * 32;
    const int warp_n0 = (wid >> 1) * 64;
    const int ar = warp_m0 + (l & 15);
    const int ac_hi = l >> 4;
    const int br = warp_n0 + (l & 7) + ((l >> 4) << 3);
    const int bc_hi = (l >> 3) & 1;

    // prologue: stages 0,1
#pragma unroll
    for (int p = 0; p < 2; ++p) {
        uint32_t b0 = smb + p * TCW_STAGE;
        load_tileA64(Ag, b0, p, t);
        load_tileB128(Bg, b0 + 8192, p, t);
        CP_COMMIT();
    }

    int st_r = 0, st_w = 2;
    for (int blk = 0; blk < 24; ++blk) {
        if (blk < 22) {
            uint32_t nb = smb + st_w * TCW_STAGE;
            load_tileA64(Ag, nb, blk + 2, t);
            load_tileB128(Bg, nb + 8192, blk + 2, t);
            CP_COMMIT();
            st_w = (st_w == 2) ? 0 : st_w + 1;
        }
        if (blk <= 21) CP_WAIT(2);
        else if (blk == 22) CP_WAIT(1);
        else CP_WAIT(0);
        __syncthreads();

        uint32_t AB = smb + st_r * TCW_STAGE;
        uint32_t BB = AB + 8192;
#pragma unroll
        for (int ks = 0; ks < 4; ++ks) {
            uint32_t a_r[2][4];
#pragma unroll
            for (int mt = 0; mt < 2; ++mt) {
                int r = ar + mt * 16;
                int c = ks * 2 + ac_hi;
                LDSM4(a_r[mt], AB + r * 128 + ((c ^ (r & 7)) << 4));
            }
            uint32_t b_r[4][4];
#pragma unroll
            for (int np = 0; np < 4; ++np) {
                int r = br + np * 16;
                int c = ks * 2 + bc_hi;
                LDSM4(b_r[np], BB + r * 128 + ((c ^ (r & 7)) << 4));
            }
#pragma unroll
            for (int mt = 0; mt < 2; ++mt)
#pragma unroll
                for (int np = 0; np < 4; ++np)
#pragma unroll
                    for (int hf = 0; hf < 2; ++hf)
                        MMA16816(acc[mt][np * 2 + hf], a_r[mt],
                                 b_r[np][hf * 2], b_r[np][hf * 2 + 1]);
        }
        __syncthreads();
        st_r = (st_r == 2) ? 0 : st_r + 1;
    }

    const int row0 = mblk * 64 + warp_m0 + (l >> 2);
    const int col0 = nblk * 128 + warp_n0 + (l & 3) * 2;
#pragma unroll
    for (int mt = 0; mt < 2; ++mt) {
#pragma unroll
        for (int nt = 0; nt < 8; ++nt) {
            int rr = row0 + mt * 16;
            int cc = col0 + nt * 8;
            float2 bv = *(const float2*)(bias + cc);
            float2 o0, o1;
            o0.x = acc[mt][nt][0] + bv.x;
            o0.y = acc[mt][nt][1] + bv.y;
            o1.x = acc[mt][nt][2] + bv.x;
            o1.y = acc[mt][nt][3] + bv.y;
            *(float2*)(out + (size_t)rr * G4x + cc) = o0;
            *(float2*)(out + (size_t)(rr + 8) * G4x + cc) = o1;
        }
    }
}

// ---------------- 3. persistent forward recurrence ------------------------------
// dedup smem (96 KB, occ 1) + kc-local gates + group barrier for h.
// Per step: [cp.async h | GEMM | part write (parity s&1) | GLOBAL barrier |
//            gates (units of own kc slice; read all-kc partials, parity s&1) |
//            GROUP barrier (24 CTAs)].
#define FWD_SMEM 98304
#define HP2 512

__device__ __forceinline__ uint32_t swadr2(uint32_t base, int r, int chunk) {
    return base + r * HP2 + ((chunk ^ (r & 7)) << 4);
}

__global__ __launch_bounds__(256, 1)
void fwd_persistent(const float* __restrict__ Wh, const float* __restrict__ bh) {
    extern __shared__ char smraw[];
    const uint32_t HB = smem_u32(smraw);
    const uint32_t WB = HB + 32768;

    const int t = threadIdx.x;
    const int l = t & 31;
    const int wid = t >> 5;
    const int bid = blockIdx.x;
    const int nblk = bid % 24;
    const int kc = bid / 24;
    unsigned int gen = ld_acq(&g_bar_gen);       // monotonic seed (global)
    unsigned int ggen = ld_acq(&g_gflags[bid]);  // monotonic seed (group)

    // zero hidden hi/lo
    for (int i = bid * 256 + t; i < NUNIT; i += NTHR) {
        __stcg(&g_hhi[i], 0u);
        __stcg(&g_hlo[i], 0u);
    }

    // one-time W tile split: Wsm[n][hi|lo] from Wh[kc*128+k][nblk*128+n]
    for (int idx = t; idx < 128 * 128; idx += 256) {
        int n = idx & 127;
        int k = idx >> 7;
        float v = Wh[(size_t)(kc * 128 + k) * G4x + nblk * 128 + n];
        __nv_bfloat16 hb = __float2bfloat16_rn(v);
        float hvf = __bfloat162float(hb);
        __nv_bfloat16 lb = __float2bfloat16_rn(v - hvf);
        int ch = k >> 3, in8 = (k & 7) << 1;
        sst16(swadr2(WB, n, ch) + in8, *(unsigned short*)&hb);
        sst16(swadr2(WB, n, 16 + ch) + in8, *(unsigned short*)&lb);
    }

    // gates: kc-local units. Group kc owns 4096 units (b x 64 j within slice);
    // CTA nblk takes contiguous range of 170-171.
    const int gstart = (4096 * nblk) / 24;
    const int gend = (4096 * (nblk + 1)) / 24;
    const int gidx = gstart + t;
    const bool act = (t < gend - gstart);
    int gb = 0, gj = 0, u = 0;
    float2 bh2[4];
    float c0 = 0.0f, c1 = 0.0f;
    if (act) {
        gb = gidx >> 6;                  // b in 0..63
        int jo = gidx & 63;              // j offset within kc slice
        int j = kc * 64 + jo;            // unit j in 0..383
        u = gb * 384 + j;                // g_hhi/g_hlo unit index
        gj = j * 2;                      // element offset within H row
#pragma unroll
        for (int gi = 0; gi < 4; ++gi)
            bh2[gi] = *(const float2*)(bh + gj + gi * Hx);
    }

    // mma addressing: 8 warps = 2 m-groups x 4 n-groups
    const int mg = wid >> 2;
    const int ng = wid & 3;
    const int ar_ = mg * 32 + (l & 15);
    const int ac_hi = l >> 4;
    const int br_ = ng * 32 + (l & 7) + ((l >> 4) << 3);
    const int bc_hi = (l >> 3) & 1;

    // prefetch xf for s=0
    float2 xf2[4];
    if (act) {
        const float* xfp = g_xf + (size_t)gb * G4x + gj;
#pragma unroll
        for (int gi = 0; gi < 4; ++gi)
            xf2[gi] = __ldcs((const float2*)(xfp + gi * Hx));
    }

    gsync(gen);  // W tile + zeroed h visible everywhere

    for (int s = 0; s < Sx; ++s) {
        const size_t pb = (size_t)(s & 1) * PARTSZ;

        // cp.async h tiles: [hi | lo] from g_hhi/g_hlo (bf16 pairs), 32 KB
#pragma unroll
        for (int q = 0; q < 8; ++q) {
            int idx2 = t + 256 * (q & 3);  // < 1024
            int region = q >> 2;           // 0:hi 1:lo
            int b = idx2 >> 4, c16 = idx2 & 15;
            const char* src =
                (const char*)(region ? g_hlo : g_hhi) + b * 1536 +
                kc * 256 + c16 * 16;
            cp16(swadr2(HB, b, region * 16 + c16), src);
        }
        CP_COMMIT();
        CP_WAIT(0);
        __syncthreads();

        // mma GEMM: per k16-chunk load 4 fragment sets, 3 products each
        float acc[2][4][4];
#pragma unroll
        for (int i = 0; i < 2; ++i)
#pragma unroll
            for (int j = 0; j < 4; ++j)
#pragma unroll
                for (int q = 0; q < 4; ++q) acc[i][j][q] = 0.0f;

#pragma unroll
        for (int c8 = 0; c8 < 8; ++c8) {
            uint32_t aH[2][4], aL[2][4];
#pragma unroll
            for (int mt = 0; mt < 2; ++mt) {
                int r = ar_ + mt * 16;
                int cH = c8 * 2 + ac_hi;
                int cL = (8 + c8) * 2 + ac_hi;
                LDSM4(aH[mt], HB + r * HP2 + ((cH ^ (r & 7)) << 4));
                LDSM4(aL[mt], HB + r * HP2 + ((cL ^ (r & 7)) << 4));
            }
            uint32_t bH[2][4], bL[2][4];
#pragma unroll
            for (int np = 0; np < 2; ++np) {
                int r = br_ + np * 16;
                int cH = c8 * 2 + bc_hi;
                int cL = (8 + c8) * 2 + bc_hi;
                LDSM4(bH[np], WB + r * HP2 + ((cH ^ (r & 7)) << 4));
                LDSM4(bL[np], WB + r * HP2 + ((cL ^ (r & 7)) << 4));
            }
#pragma unroll
            for (int mt = 0; mt < 2; ++mt) {
#pragma unroll
                for (int np = 0; np < 2; ++np) {
#pragma unroll
                    for (int hf = 0; hf < 2; ++hf) {
                        int nt = np * 2 + hf;
                        MMA16816(acc[mt][nt], aH[mt], bH[np][hf * 2],
                                 bH[np][hf * 2 + 1]);
                        MMA16816(acc[mt][nt], aL[mt], bH[np][hf * 2],
                                 bH[np][hf * 2 + 1]);
                        MMA16816(acc[mt][nt], aH[mt], bL[np][hf * 2],
                                 bL[np][hf * 2 + 1]);
                    }
                }
            }
        }

        // epilogue -> g_part[pb][kc][b][n] (L2-coherent)
        {
            const int row0 = mg * 32 + (l >> 2);
            const int col0 = nblk * 128 + ng * 32 + (l & 3) * 2;
#pragma unroll
            for (int mt = 0; mt < 2; ++mt) {
#pragma unroll
                for (int nt = 0; nt < 4; ++nt) {
                    int b = row0 + mt * 16;
                    int n = col0 + nt * 8;
                    float2 v0 = {acc[mt][nt][0], acc[mt][nt][1]};
                    float2 v1 = {acc[mt][nt][2], acc[mt][nt][3]};
                    __stcg((float2*)(g_part + pb +
                                     ((size_t)(kc * Bx + b)) * G4x + n), v0);
                    __stcg((float2*)(g_part + pb +
                                     ((size_t)(kc * Bx + b + 8)) * G4x + n), v1);
                }
            }
        }
        gsync(gen);  // all partials of step s visible

        // gates (kc-local units; MUFU transcendentals)
        if (act) {
            float g0[4], g1[4];
#pragma unroll
            for (int gi = 0; gi < 4; ++gi) {
                float v0 = xf2[gi].x + bh2[gi].x;
                float v1 = xf2[gi].y + bh2[gi].y;
                const float* pp = g_part + pb + (size_t)gb * G4x + gj + gi * Hx;
#pragma unroll
                for (int kcc = 0; kcc < 6; ++kcc) {
                    float2 pv = __ldcg((const float2*)(pp + (size_t)kcc *
                                                       (Bx * G4x)));
                    v0 += pv.x;
                    v1 += pv.y;
                }
                g0[gi] = v0;
                g1[gi] = v1;
            }
            float r0 = fsigm(g0[0]), f0 = fsigm(g0[1]);
            float t0 = ftanh(g0[2]), o0 = fsigm(g0[3]);
            float r1 = fsigm(g1[0]), f1 = fsigm(g1[1]);
            float t1 = ftanh(g1[2]), o1 = fsigm(g1[3]);
            c0 = f0 * c0 + r0 * t0;
            c1 = f1 * c1 + r1 * t1;
            float h0 = o0 * ftanh(c0);
            float h1 = o1 * ftanh(c1);
            float2 h2 = {h0, h1};
            *(float2*)(g_hsf + (size_t)s * (Bx * Hx) + gb * Hx + gj) = h2;
            float hr0 = __bfloat162float(__float2bfloat16_rn(h0));
            float hr1 = __bfloat162float(__float2bfloat16_rn(h1));
            __stcg(&g_hhi[u], packbf2(h0, h1));
            __stcg(&g_hlo[u], packbf2(h0 - hr0, h1 - hr1));
            // prefetch xf for next step (independent of the barrier below)
            if (s + 1 < Sx) {
                const float* xfp = g_xf + ((size_t)(s + 1) * Bx + gb) * G4x + gj;
#pragma unroll
                for (int gi = 0; gi < 4; ++gi)
                    xf2[gi] = __ldcs((const float2*)(xfp + gi * Hx));
            }
        }
        gsync_group(ggen, kc);  // our kc h-slice ready (written by own group)
    }
}

// ---------------- 4. one-shot hidden GEMM for hT @ Wh_b (split-K partials) ----
__global__ __launch_bounds__(256, 2)
void step_gemm_kernel(const float* __restrict__ Wh) {
    __shared__ float hsT[16][68];
    __shared__ float Wsm[16][128];
    const float* hsrc = g_hsf + (size_t)(Sx - 1) * Bx * Hx;  // hT = hsf[511]
    const int t = threadIdx.x;
    const int nblk = blockIdx.x;  // 24
    const int kc = blockIdx.y;    // 6
    const float* Wb = Wh + nblk * 128;

    unsigned long long acc[4][4];
#pragma unroll
    for (int i = 0; i < 4; ++i)
#pragma unroll
        for (int j = 0; j < 4; ++j) acc[i][j] = 0ull;

    const int la_b = t >> 2;
    const int la_k = (t & 3) * 4;
    const int lb_k = t >> 5;
    const int lb_n = (t & 31) * 4;
    const int b0 = (t >> 4) * 4;
    const int n0 = (t & 15) * 8;

    for (int kt = 0; kt < 8; ++kt) {
        int k0 = kc * 128 + kt * 16;
        float4 va = *(const float4*)(hsrc + la_b * Hx + k0 + la_k);
        float4 vb0 = *(const float4*)(Wb + (size_t)(k0 + lb_k) * G4x + lb_n);
        float4 vb1 = *(const float4*)(Wb + (size_t)(k0 + lb_k + 8) * G4x + lb_n);
        hsT[la_k + 0][la_b] = va.x; hsT[la_k + 1][la_b] = va.y;
        hsT[la_k + 2][la_b] = va.z; hsT[la_k + 3][la_b] = va.w;
        *(float4*)(&Wsm[lb_k][lb_n]) = vb0;
        *(float4*)(&Wsm[lb_k + 8][lb_n]) = vb1;
        __syncthreads();
#pragma unroll
        for (int k = 0; k < 16; ++k) {
            float a[4];
            *(float4*)a = *(const float4*)(&hsT[k][b0]);
            ulonglong2 b01 = *(const ulonglong2*)(&Wsm[k][n0]);
            ulonglong2 b23 = *(const ulonglong2*)(&Wsm[k][n0 + 4]);
            unsigned long long bb0 = b01.x, bb1 = b01.y, bb2 = b23.x, bb3 = b23.y;
#pragma unroll
            for (int i = 0; i < 4; ++i) {
                unsigned long long a2 = pack2(a[i]);
                fma2(acc[i][0], a2, bb0);
                fma2(acc[i][1], a2, bb1);
                fma2(acc[i][2], a2, bb2);
                fma2(acc[i][3], a2, bb3);
            }
        }
        __syncthreads();
    }
#pragma unroll
    for (int i = 0; i < 4; ++i) {
#pragma unroll
        for (int j = 0; j < 4; ++j) {
            float2 v = unpack2(acc[i][j]);
            int gn = nblk * 128 + n0 + j * 2;
            *(float2*)(g_part + ((size_t)(kc * Bx + b0 + i)) * G4x + gn) = v;
        }
    }
}

// ---------------- 5. backward (constant-hT) scan --------------------------------
__global__ void bscan_kernel(const float* __restrict__ bh) {
    int idx = blockIdx.x * 256 + threadIdx.x;  // < 49152
    int b = idx / Hx;
    int j = idx - b * Hx;
    float hw[4];
#pragma unroll
    for (int gi = 0; gi < 4; ++gi) {
        int col = j + gi * Hx;
        float v = bh[col];
#pragma unroll
        for (int kc = 0; kc < 6; ++kc)
            v += g_part[((size_t)(kc * Bx + b)) * G4x + col];
        hw[gi] = v;
    }
    float c2 = 0.f;
#pragma unroll 4
    for (int s = Sx - 1; s >= 0; --s) {
        const float* gbp = g_gb + ((size_t)s * Bx + b) * G4x + j;
        float r = fsigm(__ldcs(gbp) + hw[0]);
        float f = fsigm(__ldcs(gbp + Hx) + hw[1]);
        float gg = ftanh(__ldcs(gbp + 2 * Hx) + hw[2]);
        float o = fsigm(__ldcs(gbp + 3 * Hx) + hw[3]);
        c2 = f * c2 + r * gg;
        g_hsb[(size_t)s * (Bx * Hx) + idx] = o * ftanh(c2);
    }
}

// ---------------- 6. output GEMM + pad bias -------------------------------------
__global__ __launch_bounds__(256, 2)
void out_kernel(const float* __restrict__ Wout, const float* __restrict__ bout,
                const int* __restrict__ tokens, float* __restrict__ out) {
    __shared__ float As[64][65];
    __shared__ float Wsm[64][33];
    const int t = threadIdx.x;
    const int rb = blockIdx.x;  // 512
    const int l = t & 31;
    const int rg = t >> 5;  // 0..7
    float acc[8];
#pragma unroll
    for (int i = 0; i < 8; ++i) acc[i] = 0.f;

    for (int kt = 0; kt < 24; ++kt) {
        int k0 = kt * 64;
        const float* src_base = (k0 < Hx) ? g_hsf : g_hsb;
        int koff = (k0 < Hx) ? k0 : (k0 - Hx);
#pragma unroll
        for (int q = 0; q < 4; ++q) {
            int i = t + 256 * q;
            int row = i >> 4;
            int kq = (i & 15) * 4;
            const float* src =
                src_base + ((size_t)(rb * 64 + row)) * Hx + koff + kq;
            float4 v = *(const float4*)src;
            As[row][kq] = v.x; As[row][kq + 1] = v.y;
            As[row][kq + 2] = v.z; As[row][kq + 3] = v.w;
        }
#pragma unroll
        for (int q = 0; q < 2; ++q) {
            int i = t + 256 * q;
            int k = i >> 3;
            int lq = (i & 7) * 4;
            float4 v = *(const float4*)(Wout + (size_t)(k0 + k) * 32 + lq);
            Wsm[k][lq] = v.x; Wsm[k][lq + 1] = v.y;
            Wsm[k][lq + 2] = v.z; Wsm[k][lq + 3] = v.w;
        }
        __syncthreads();
#pragma unroll 8
        for (int k = 0; k < 64; ++k) {
            float w = Wsm[k][l];
#pragma unroll
            for (int i = 0; i < 8; ++i) acc[i] += As[rg * 8 + i][k] * w;
        }
        __syncthreads();
    }
#pragma unroll
    for (int i = 0; i < 8; ++i) {
        int row = rb * 64 + rg * 8 + i;
        float v = acc[i] + bout[l];
        if (l == 0 && tokens[row] == 1) v += 10000.0f;
        out[(size_t)row * 32 + l] = v;
    }
}

// ---------------- launch ---------------------------------------------------------
extern "C" void kernel_launch(void* const* d_in, const int* in_sizes, int n_in,
                              void* d_out, int out_size) {
    (void)in_sizes; (void)n_in; (void)out_size;
    const int* tokens = (const int*)d_in[0];
    const float* embedding = (const float*)d_in[2];
    const float* Wi_f = (const float*)d_in[3];
    const float* bi_f = (const float*)d_in[4];
    const float* Wh_f = (const float*)d_in[5];
    const float* bh_f = (const float*)d_in[6];
    const float* Wi_b = (const float*)d_in[7];
    const float* bi_b = (const float*)d_in[8];
    const float* Wh_b = (const float*)d_in[9];
    const float* bh_b = (const float*)d_in[10];
    const float* Wout = (const float*)d_in[11];
    const float* bout = (const float*)d_in[12];
    float* out = (float*)d_out;

    cudaFuncSetAttribute(fwd_persistent,
                         cudaFuncAttributeMaxDynamicSharedMemorySize, FWD_SMEM);
    cudaFuncSetAttribute(tcw_gemm,
                         cudaFuncAttributeMaxDynamicSharedMemorySize, TCW_SMEM);

    // 1. gather embeddings into compensated bf16 layout [Ah|Al]
    embed_split_kernel<<<SBx * 64 / 256, 256>>>(tokens, embedding);
    // 2. input projections via single uniform bf16 MMA GEMM (K=1536, 3-stage)
    wsplit_kernel<<<dim3(16, 96), 256>>>(Wi_f, 0);
    wsplit_kernel<<<dim3(16, 96), 256>>>(Wi_b, 1);
    tcw_gemm<<<dim3(24, 512), 128, TCW_SMEM>>>(bi_f, 0);
    tcw_gemm<<<dim3(24, 512), 128, TCW_SMEM>>>(bi_b, 1);
    // 3. forward LSTM recurrence (kc-local gates + group barrier for h)
    fwd_persistent<<<NCTA, 256, FWD_SMEM>>>(Wh_f, bh_f);
    // 4. hT @ Wh_b partials
    step_gemm_kernel<<<dim3(24, 6), 256>>>(Wh_b);
    // 5. backward scan
    bscan_kernel<<<192, 256>>>(bh_b);
    // 6. output projection + pad bias
    out_kernel<<<512, 256>>>(Wout, bout, tokens, out);
}

// round 15
// speedup vs baseline: 1.3675x; 1.3675x over previous
#include <cuda_runtime.h>
#include <cuda_bf16.h>
#include <cstdint>

// Problem constants
#define Sx 512
#define Bx 64
#define Ex 512
#define Hx 768
#define G4x 3072
#define SBx 32768      // Sx*Bx
#define KX 1536        // tripled-K for compensated bf16 GEMM (B side)
#define AX 1024        // A side: [Ah | Al] only
#define NCTA 144       // fwd persistent grid (24 nblk x 6 kc)
#define NTHR 36864     // NCTA*256
#define NUNIT 24576    // Bx*Hx/2 gate units (float2)
#define FPAD 32        // flag padding: 32 words = 128B per flag

// ---------------- scratch (device globals: allocation-guard-safe) -------------
__device__ __nv_bfloat16 g_ax[(size_t)SBx * AX];    // 67 MB   [Ah | Al]
__device__ __nv_bfloat16 g_bxf[(size_t)G4x * KX];   // 9.4 MB  [Bh ; Bh ; Bl] fwd
__device__ __nv_bfloat16 g_bxb[(size_t)G4x * KX];   // 9.4 MB  [Bh ; Bh ; Bl] bwd
__device__ float g_xf[(size_t)SBx * G4x];    // 402 MB  emb@Wi_f + bi_f     [SB,4H]
__device__ float g_gb[(size_t)SBx * G4x];    // 402 MB  emb@Wi_b + bi_b     [SB,4H]
__device__ float g_hsf[(size_t)SBx * Hx];    // 100 MB  forward hiddens     [S,B,H]
__device__ float g_hsb[(size_t)SBx * Hx];    // 100 MB  backward hiddens    [S,B,H]
__device__ float g_part[6 * Bx * G4x];       // 4.7 MB  split-K partials [6,B,4H]
__device__ uint32_t g_hhi[NUNIT];            // current hidden hi (bf16x2)
__device__ uint32_t g_hlo[NUNIT];            // current hidden lo (bf16x2)
__device__ unsigned int g_flags[NCTA * FPAD];  // padded per-CTA barrier gens
__device__ unsigned int g_bar_gen;             // broadcast generation

// ---------------- f32x2 helpers (for step_gemm one-shot) -----------------------
__device__ __forceinline__ void fma2(unsigned long long& d, unsigned long long a,
                                     unsigned long long b) {
    asm("fma.rn.f32x2 %0, %1, %2, %0;" : "+l"(d) : "l"(a), "l"(b));
}
__device__ __forceinline__ unsigned long long pack2(float x) {
    unsigned long long r;
    asm("mov.b64 %0, {%1, %1};" : "=l"(r) : "f"(x));
    return r;
}
__device__ __forceinline__ float2 unpack2(unsigned long long v) {
    float2 f;
    asm("mov.b64 {%0, %1}, %2;" : "=f"(f.x), "=f"(f.y) : "l"(v));
    return f;
}

// ---------------- fast transcendentals (MUFU, rel err ~3e-7) -------------------
__device__ __forceinline__ float fsigm(float x) {
    float t, r;
    asm("ex2.approx.f32 %0, %1;" : "=f"(t) : "f"(-1.4426950408889634f * x));
    asm("rcp.approx.f32 %0, %1;" : "=f"(r) : "f"(1.0f + t));
    return r;
}
__device__ __forceinline__ float ftanh(float x) {
    return fmaf(2.0f, fsigm(2.0f * x), -1.0f);
}

// ---------------- misc helpers --------------------------------------------------
__device__ __forceinline__ uint32_t smem_u32(const void* p) {
    uint32_t a;
    asm("{ .reg .u64 t; cvta.to.shared.u64 t, %1; cvt.u32.u64 %0, t; }"
        : "=r"(a) : "l"(p));
    return a;
}
__device__ __forceinline__ void st_rel(unsigned int* p, unsigned int v) {
    asm volatile("st.release.gpu.global.u32 [%0], %1;" :: "l"(p), "r"(v) : "memory");
}
__device__ __forceinline__ unsigned int ld_acq(const unsigned int* p) {
    unsigned int v;
    asm volatile("ld.acquire.gpu.global.u32 %0, [%1];" : "=r"(v) : "l"(p) : "memory");
    return v;
}

// grid barrier: per-CTA padded flag release; CTA0 aggregates (1 thread per flag,
// each flag on its own 128B line) and broadcasts; others poll broadcast word.
__device__ __forceinline__ void gsync(unsigned int& gen) {
    __syncthreads();
    gen++;
    if (threadIdx.x == 0) {
        st_rel(&g_flags[blockIdx.x * FPAD], gen);  // release orders prior writes
    }
    if (blockIdx.x == 0) {
        if (threadIdx.x < NCTA) {
            while ((int)(ld_acq(&g_flags[threadIdx.x * FPAD]) - gen) < 0) {}
        }
        __syncthreads();
        if (threadIdx.x == 0) st_rel(&g_bar_gen, gen);
    } else {
        if (threadIdx.x == 0) {
            while ((int)(ld_acq(&g_bar_gen) - gen) < 0) {}
        }
    }
    __syncthreads();
}

// ---------------- mma.sync / ldmatrix / cp.async macros -------------------------
#define LDSM4(r, addr) \
    asm volatile("ldmatrix.sync.aligned.m8n8.x4.shared.b16 {%0,%1,%2,%3}, [%4];" \
                 : "=r"((r)[0]), "=r"((r)[1]), "=r"((r)[2]), "=r"((r)[3]) \
                 : "r"(addr))
#define MMA16816(c, a, b0v, b1v) \
    asm volatile("mma.sync.aligned.m16n8k16.row.col.f32.bf16.bf16.f32 " \
                 "{%0,%1,%2,%3}, {%4,%5,%6,%7}, {%8,%9}, {%0,%1,%2,%3};" \
                 : "+f"((c)[0]), "+f"((c)[1]), "+f"((c)[2]), "+f"((c)[3]) \
                 : "r"((a)[0]), "r"((a)[1]), "r"((a)[2]), "r"((a)[3]), \
                   "r"(b0v), "r"(b1v))
__device__ __forceinline__ void cp16(uint32_t dst, const void* src) {
    asm volatile("cp.async.cg.shared.global [%0], [%1], 16;"
                 :: "r"(dst), "l"(src));
}
#define CP_COMMIT() asm volatile("cp.async.commit_group;" ::: "memory")
#define CP_WAIT(n) asm volatile("cp.async.wait_group %0;" :: "n"(n) : "memory")
__device__ __forceinline__ void sst16(uint32_t addr, unsigned short v) {
    asm volatile("st.shared.b16 [%0], %1;" :: "r"(addr), "h"(v));
}

// ---------------- 1. embedding gather + compensated layout ---------------------
__device__ __forceinline__ uint32_t packbf2(float a, float b) {
    __nv_bfloat162 t = __floats2bfloat162_rn(a, b);
    return *(uint32_t*)&t;
}
__global__ void embed_split_kernel(const int* __restrict__ tokens,
                                   const float* __restrict__ embedding) {
    int idx = blockIdx.x * blockDim.x + threadIdx.x;  // over SB * 64 (8 elems each)
    int e8 = idx & 63;
    int sb = idx >> 6;
    int tok = tokens[sb];
    const float4* src = (const float4*)(embedding + (size_t)tok * Ex + e8 * 8);
    float4 v0 = src[0], v1 = src[1];
    float hv[8], lo[8];
    float in[8] = {v0.x, v0.y, v0.z, v0.w, v1.x, v1.y, v1.z, v1.w};
#pragma unroll
    for (int i = 0; i < 8; ++i) {
        hv[i] = __bfloat162float(__float2bfloat16_rn(in[i]));
        lo[i] = in[i] - hv[i];
    }
    uint4 ph, pl;
    ph.x = packbf2(in[0], in[1]); ph.y = packbf2(in[2], in[3]);
    ph.z = packbf2(in[4], in[5]); ph.w = packbf2(in[6], in[7]);
    pl.x = packbf2(lo[0], lo[1]); pl.y = packbf2(lo[2], lo[3]);
    pl.z = packbf2(lo[4], lo[5]); pl.w = packbf2(lo[6], lo[7]);
    size_t off = (size_t)sb * AX + e8 * 8;
    *(uint4*)(g_ax + off) = ph;
    *(uint4*)(g_ax + off + 512) = pl;
}

// ---------------- 1b. W transpose + compensated layout --------------------------
__global__ void wsplit_kernel(const float* __restrict__ W, int which) {
    __shared__ float tile[32][33];
    __nv_bfloat16* dst = which ? g_bxb : g_bxf;
    const int kb = blockIdx.x;  // 16
    const int nb = blockIdx.y;  // 96
    const int t = threadIdx.x;
    const int c = t & 31;
    const int r0 = t >> 5;  // 0..7
#pragma unroll
    for (int q = 0; q < 4; ++q) {
        int r = r0 + 8 * q;
        tile[r][c] = W[(size_t)(kb * 32 + r) * G4x + nb * 32 + c];
    }
    __syncthreads();
#pragma unroll
    for (int q = 0; q < 4; ++q) {
        int i = r0 + 8 * q;            // n within tile
        float v = tile[c][i];          // W[kb*32+c][nb*32+i]
        __nv_bfloat16 hb = __float2bfloat16_rn(v);
        float hvf = __bfloat162float(hb);
        size_t off = (size_t)(nb * 32 + i) * KX + kb * 32 + c;
        dst[off] = hb;
        dst[off + 512] = hb;
        dst[off + 1024] = __float2bfloat16_rn(v - hvf);
    }
}

// ---------------- 2. warp-MMA input GEMM (uniform bf16, K=1536, 3-stage) --------
// 128-thread CTAs, tile 64m x 128n, BK=64, 3 CTAs/SM co-resident. (measured best)
#define TCW_STAGE 24576                 // A 8KB + B 16KB
#define TCW_SMEM (3 * TCW_STAGE)        // 72 KB

__device__ __forceinline__ void load_tileA64(const __nv_bfloat16* __restrict__ g,
                                             uint32_t sbase, int blk, int t) {
    int aoff = (blk < 16 ? blk : blk - 16) * 128;  // byte offset in 2048B row
#pragma unroll
    for (int q = 0; q < 4; ++q) {
        int idx = t + 128 * q;         // < 512 : 64 rows x 8 chunks
        int r = idx >> 3, c = idx & 7;
        const char* src = (const char*)g + (size_t)r * (AX * 2) + aoff + c * 16;
        uint32_t dst = sbase + r * 128 + ((c ^ (r & 7)) << 4);
        cp16(dst, src);
    }
}
__device__ __forceinline__ void load_tileB128(const __nv_bfloat16* __restrict__ g,
                                              uint32_t sbase, int blk, int t) {
#pragma unroll
    for (int q = 0; q < 8; ++q) {
        int idx = t + 128 * q;         // < 1024 : 128 rows x 8 chunks
        int r = idx >> 3, c = idx & 7;
        const char* src = (const char*)g + (size_t)r * (KX * 2) + blk * 128 + c * 16;
        uint32_t dst = sbase + r * 128 + ((c ^ (r & 7)) << 4);
        cp16(dst, src);
    }
}

__global__ __launch_bounds__(128, 2)
void tcw_gemm(const float* __restrict__ bias, int which) {
    extern __shared__ char smraw[];
    uint32_t smb = smem_u32(smraw);
    const int t = threadIdx.x;
    const int l = t & 31;
    const int wid = t >> 5;            // 0..3
    const int nblk = blockIdx.x;       // 24
    const int mblk = blockIdx.y;       // 512 (rows of 64)

    const __nv_bfloat16* Ag = g_ax + (size_t)mblk * 64 * AX;
    const __nv_bfloat16* Bg = (which ? g_bxb : g_bxf) + (size_t)nblk * 128 * KX;
    float* out = which ? g_gb : g_xf;

    float acc[2][8][4];
#pragma unroll
    for (int i = 0; i < 2; ++i)
#pragma unroll
        for (int j = 0; j < 8; ++j)
#pragma unroll
            for (int q = 0; q < 4; ++q) acc[i][j][q] = 0.0f;

    const int warp_m0 = (wid & 1) * 32;
    const int warp_n0 = (wid >> 1) * 64;
    const int ar = warp_m0 + (l & 15);
    const int ac_hi = l >> 4;
    const int br = warp_n0 + (l & 7) + ((l >> 4) << 3);
    const int bc_hi = (l >> 3) & 1;

    // prologue: stages 0,1
#pragma unroll
    for (int p = 0; p < 2; ++p) {
        uint32_t b0 = smb + p * TCW_STAGE;
        load_tileA64(Ag, b0, p, t);
        load_tileB128(Bg, b0 + 8192, p, t);
        CP_COMMIT();
    }

    int st_r = 0, st_w = 2;
    for (int blk = 0; blk < 24; ++blk) {
        if (blk < 22) {
            uint32_t nb = smb + st_w * TCW_STAGE;
            load_tileA64(Ag, nb, blk + 2, t);
            load_tileB128(Bg, nb + 8192, blk + 2, t);
            CP_COMMIT();
            st_w = (st_w == 2) ? 0 : st_w + 1;
        }
        if (blk <= 21) CP_WAIT(2);
        else if (blk == 22) CP_WAIT(1);
        else CP_WAIT(0);
        __syncthreads();

        uint32_t AB = smb + st_r * TCW_STAGE;
        uint32_t BB = AB + 8192;
#pragma unroll
        for (int ks = 0; ks < 4; ++ks) {
            uint32_t a_r[2][4];
#pragma unroll
            for (int mt = 0; mt < 2; ++mt) {
                int r = ar + mt * 16;
                int c = ks * 2 + ac_hi;
                LDSM4(a_r[mt], AB + r * 128 + ((c ^ (r & 7)) << 4));
            }
            uint32_t b_r[4][4];
#pragma unroll
            for (int np = 0; np < 4; ++np) {
                int r = br + np * 16;
                int c = ks * 2 + bc_hi;
                LDSM4(b_r[np], BB + r * 128 + ((c ^ (r & 7)) << 4));
            }
#pragma unroll
            for (int mt = 0; mt < 2; ++mt)
#pragma unroll
                for (int np = 0; np < 4; ++np)
#pragma unroll
                    for (int hf = 0; hf < 2; ++hf)
                        MMA16816(acc[mt][np * 2 + hf], a_r[mt],
                                 b_r[np][hf * 2], b_r[np][hf * 2 + 1]);
        }
        __syncthreads();
        st_r = (st_r == 2) ? 0 : st_r + 1;
    }

    const int row0 = mblk * 64 + warp_m0 + (l >> 2);
    const int col0 = nblk * 128 + warp_n0 + (l & 3) * 2;
#pragma unroll
    for (int mt = 0; mt < 2; ++mt) {
#pragma unroll
        for (int nt = 0; nt < 8; ++nt) {
            int rr = row0 + mt * 16;
            int cc = col0 + nt * 8;
            float2 bv = *(const float2*)(bias + cc);
            float2 o0, o1;
            o0.x = acc[mt][nt][0] + bv.x;
            o0.y = acc[mt][nt][1] + bv.y;
            o1.x = acc[mt][nt][2] + bv.x;
            o1.y = acc[mt][nt][3] + bv.y;
            *(float2*)(out + (size_t)rr * G4x + cc) = o0;
            *(float2*)(out + (size_t)(rr + 8) * G4x + cc) = o1;
        }
    }
}

// ---------------- 3. persistent forward recurrence (dedup smem, occ 1) ----------
// CTA (nblk = bid%24, kc = bid/24). smem 96 KB, 1 CTA/SM, FULL registers:
//   Hsm [64 b][32 ch]  = 32 KB : chunks 0-15 = h_hi, 16-31 = h_lo
//   Wsm [128 n][32 ch] = 64 KB : chunks 0-15 = W_hi, 16-31 = W_lo
// Per k16-chunk: load Ah/Al/Bh/Bl fragments once (8 LDSM), issue all three
// compensation products (Ah*Bh + Al*Bh + Ah*Bl) from registers.
#define FWD_SMEM 98304
#define HP2 512

__device__ __forceinline__ uint32_t swadr2(uint32_t base, int r, int chunk) {
    return base + r * HP2 + ((chunk ^ (r & 7)) << 4);
}

__global__ __launch_bounds__(256, 1)
void fwd_persistent(const float* __restrict__ Wh, const float* __restrict__ bh) {
    extern __shared__ char smraw[];
    const uint32_t HB = smem_u32(smraw);
    const uint32_t WB = HB + 32768;

    const int t = threadIdx.x;
    const int l = t & 31;
    const int wid = t >> 5;
    const int bid = blockIdx.x;
    const int nblk = bid % 24;
    const int kc = bid / 24;
    unsigned int gen = ld_acq(&g_bar_gen);  // monotonic seed

    // zero hidden hi/lo
    for (int i = bid * 256 + t; i < NUNIT; i += NTHR) {
        __stcg(&g_hhi[i], 0u);
        __stcg(&g_hlo[i], 0u);
    }

    // one-time W tile split: Wsm[n][hi|lo] from Wh[kc*128+k][nblk*128+n]
    for (int idx = t; idx < 128 * 128; idx += 256) {
        int n = idx & 127;
        int k = idx >> 7;
        float v = Wh[(size_t)(kc * 128 + k) * G4x + nblk * 128 + n];
        __nv_bfloat16 hb = __float2bfloat16_rn(v);
        float hvf = __bfloat162float(hb);
        __nv_bfloat16 lb = __float2bfloat16_rn(v - hvf);
        int ch = k >> 3, in8 = (k & 7) << 1;
        sst16(swadr2(WB, n, ch) + in8, *(unsigned short*)&hb);
        sst16(swadr2(WB, n, 16 + ch) + in8, *(unsigned short*)&lb);
    }

    // gates: balanced contiguous unit ranges, 170-171 units per CTA
    const int ustart = (512 * bid) / 3;
    const int uend = (512 * (bid + 1)) / 3;
    const int u = ustart + t;
    const bool act = (t < uend - ustart);
    int gb = 0, gj = 0;
    float2 bh2[4];
    float c0 = 0.0f, c1 = 0.0f;
    if (act) {
        gb = u / 384;
        gj = (u - gb * 384) * 2;
#pragma unroll
        for (int gi = 0; gi < 4; ++gi)
            bh2[gi] = *(const float2*)(bh + gj + gi * Hx);
    }

    // mma addressing: 8 warps = 2 m-groups x 4 n-groups
    const int mg = wid >> 2;
    const int ng = wid & 3;
    const int ar_ = mg * 32 + (l & 15);
    const int ac_hi = l >> 4;
    const int br_ = ng * 32 + (l & 7) + ((l >> 4) << 3);
    const int bc_hi = (l >> 3) & 1;

    // prefetch xf for s=0 (independent of recurrence state)
    float2 xf2[4];
    if (act) {
        const float* xfp = g_xf + (size_t)gb * G4x + gj;
#pragma unroll
        for (int gi = 0; gi < 4; ++gi)
            xf2[gi] = __ldcs((const float2*)(xfp + gi * Hx));
    }

    gsync(gen);  // W tile + zeroed h visible everywhere

    for (int s = 0; s < Sx; ++s) {
        // cp.async h tiles: [hi | lo] from g_hhi/g_hlo (bf16 pairs), 32 KB
#pragma unroll
        for (int q = 0; q < 8; ++q) {
            int idx2 = t + 256 * (q & 3);  // < 1024
            int region = q >> 2;           // 0:hi 1:lo
            int b = idx2 >> 4, c16 = idx2 & 15;
            const char* src =
                (const char*)(region ? g_hlo : g_hhi) + b * 1536 +
                kc * 256 + c16 * 16;
            cp16(swadr2(HB, b, region * 16 + c16), src);
        }
        CP_COMMIT();
        CP_WAIT(0);
        __syncthreads();

        // mma GEMM: per k16-chunk load 4 fragment sets, 3 products each
        float acc[2][4][4];
#pragma unroll
        for (int i = 0; i < 2; ++i)
#pragma unroll
            for (int j = 0; j < 4; ++j)
#pragma unroll
                for (int q = 0; q < 4; ++q) acc[i][j][q] = 0.0f;

#pragma unroll
        for (int c8 = 0; c8 < 8; ++c8) {
            uint32_t aH[2][4], aL[2][4];
#pragma unroll
            for (int mt = 0; mt < 2; ++mt) {
                int r = ar_ + mt * 16;
                int cH = c8 * 2 + ac_hi;
                int cL = (8 + c8) * 2 + ac_hi;
                LDSM4(aH[mt], HB + r * HP2 + ((cH ^ (r & 7)) << 4));
                LDSM4(aL[mt], HB + r * HP2 + ((cL ^ (r & 7)) << 4));
            }
            uint32_t bH[2][4], bL[2][4];
#pragma unroll
            for (int np = 0; np < 2; ++np) {
                int r = br_ + np * 16;
                int cH = c8 * 2 + bc_hi;
                int cL = (8 + c8) * 2 + bc_hi;
                LDSM4(bH[np], WB + r * HP2 + ((cH ^ (r & 7)) << 4));
                LDSM4(bL[np], WB + r * HP2 + ((cL ^ (r & 7)) << 4));
            }
#pragma unroll
            for (int mt = 0; mt < 2; ++mt) {
#pragma unroll
                for (int np = 0; np < 2; ++np) {
#pragma unroll
                    for (int hf = 0; hf < 2; ++hf) {
                        int nt = np * 2 + hf;
                        MMA16816(acc[mt][nt], aH[mt], bH[np][hf * 2],
                                 bH[np][hf * 2 + 1]);
                        MMA16816(acc[mt][nt], aL[mt], bH[np][hf * 2],
                                 bH[np][hf * 2 + 1]);
                        MMA16816(acc[mt][nt], aH[mt], bL[np][hf * 2],
                                 bL[np][hf * 2 + 1]);
                    }
                }
            }
        }

        // epilogue -> g_part[kc][b][n] (L2-coherent)
        {
            const int row0 = mg * 32 + (l >> 2);
            const int col0 = nblk * 128 + ng * 32 + (l & 3) * 2;
#pragma unroll
            for (int mt = 0; mt < 2; ++mt) {
#pragma unroll
                for (int nt = 0; nt < 4; ++nt) {
                    int b = row0 + mt * 16;
                    int n = col0 + nt * 8;
                    float2 v0 = {acc[mt][nt][0], acc[mt][nt][1]};
                    float2 v1 = {acc[mt][nt][2], acc[mt][nt][3]};
                    __stcg((float2*)(g_part + ((size_t)(kc * Bx + b)) * G4x + n), v0);
                    __stcg((float2*)(g_part + ((size_t)(kc * Bx + b + 8)) * G4x + n),
                           v1);
                }
            }
        }
        gsync(gen);

        // gates (one float2 unit per active thread; MUFU transcendentals)
        if (act) {
            float g0[4], g1[4];
#pragma unroll
            for (int gi = 0; gi < 4; ++gi) {
                float v0 = xf2[gi].x + bh2[gi].x;
                float v1 = xf2[gi].y + bh2[gi].y;
                const float* pp = g_part + (size_t)gb * G4x + gj + gi * Hx;
#pragma unroll
                for (int kcc = 0; kcc < 6; ++kcc) {
                    float2 pv = __ldcg((const float2*)(pp + (size_t)kcc *
                                                       (Bx * G4x)));
                    v0 += pv.x;
                    v1 += pv.y;
                }
                g0[gi] = v0;
                g1[gi] = v1;
            }
            float r0 = fsigm(g0[0]), f0 = fsigm(g0[1]);
            float t0 = ftanh(g0[2]), o0 = fsigm(g0[3]);
            float r1 = fsigm(g1[0]), f1 = fsigm(g1[1]);
            float t1 = ftanh(g1[2]), o1 = fsigm(g1[3]);
            c0 = f0 * c0 + r0 * t0;
            c1 = f1 * c1 + r1 * t1;
            float h0 = o0 * ftanh(c0);
            float h1 = o1 * ftanh(c1);
            float2 h2 = {h0, h1};
            *(float2*)(g_hsf + (size_t)s * (Bx * Hx) + gb * Hx + gj) = h2;
            float hr0 = __bfloat162float(__float2bfloat16_rn(h0));
            float hr1 = __bfloat162float(__float2bfloat16_rn(h1));
            __stcg(&g_hhi[u], packbf2(h0, h1));
            __stcg(&g_hlo[u], packbf2(h0 - hr0, h1 - hr1));
            // prefetch xf for next step (independent of the barrier below)
            if (s + 1 < Sx) {
                const float* xfp = g_xf + ((size_t)(s + 1) * Bx + gb) * G4x + gj;
#pragma unroll
                for (int gi = 0; gi < 4; ++gi)
                    xf2[gi] = __ldcs((const float2*)(xfp + gi * Hx));
            }
        }
        gsync(gen);
    }
}

// ---------------- 4. one-shot hidden GEMM for hT @ Wh_b (split-K partials) ----
__global__ __launch_bounds__(256, 2)
void step_gemm_kernel(const float* __restrict__ Wh) {
    __shared__ float hsT[16][68];
    __shared__ float Wsm[16][128];
    const float* hsrc = g_hsf + (size_t)(Sx - 1) * Bx * Hx;  // hT = hsf[511]
    const int t = threadIdx.x;
    const int nblk = blockIdx.x;  // 24
    const int kc = blockIdx.y;    // 6
    const float* Wb = Wh + nblk * 128;

    unsigned long long acc[4][4];
#pragma unroll
    for (int i = 0; i < 4; ++i)
#pragma unroll
        for (int j = 0; j < 4; ++j) acc[i][j] = 0ull;

    const int la_b = t >> 2;
    const int la_k = (t & 3) * 4;
    const int lb_k = t >> 5;
    const int lb_n = (t & 31) * 4;
    const int b0 = (t >> 4) * 4;
    const int n0 = (t & 15) * 8;

    for (int kt = 0; kt < 8; ++kt) {
        int k0 = kc * 128 + kt * 16;
        float4 va = *(const float4*)(hsrc + la_b * Hx + k0 + la_k);
        float4 vb0 = *(const float4*)(Wb + (size_t)(k0 + lb_k) * G4x + lb_n);
        float4 vb1 = *(const float4*)(Wb + (size_t)(k0 + lb_k + 8) * G4x + lb_n);
        hsT[la_k + 0][la_b] = va.x; hsT[la_k + 1][la_b] = va.y;
        hsT[la_k + 2][la_b] = va.z; hsT[la_k + 3][la_b] = va.w;
        *(float4*)(&Wsm[lb_k][lb_n]) = vb0;
        *(float4*)(&Wsm[lb_k + 8][lb_n]) = vb1;
        __syncthreads();
#pragma unroll
        for (int k = 0; k < 16; ++k) {
            float a[4];
            *(float4*)a = *(const float4*)(&hsT[k][b0]);
            ulonglong2 b01 = *(const ulonglong2*)(&Wsm[k][n0]);
            ulonglong2 b23 = *(const ulonglong2*)(&Wsm[k][n0 + 4]);
            unsigned long long bb0 = b01.x, bb1 = b01.y, bb2 = b23.x, bb3 = b23.y;
#pragma unroll
            for (int i = 0; i < 4; ++i) {
                unsigned long long a2 = pack2(a[i]);
                fma2(acc[i][0], a2, bb0);
                fma2(acc[i][1], a2, bb1);
                fma2(acc[i][2], a2, bb2);
                fma2(acc[i][3], a2, bb3);
            }
        }
        __syncthreads();
    }
#pragma unroll
    for (int i = 0; i < 4; ++i) {
#pragma unroll
        for (int j = 0; j < 4; ++j) {
            float2 v = unpack2(acc[i][j]);
            int gn = nblk * 128 + n0 + j * 2;
            *(float2*)(g_part + ((size_t)(kc * Bx + b0 + i)) * G4x + gn) = v;
        }
    }
}

// ---------------- 5. backward (constant-hT) scan --------------------------------
__global__ void bscan_kernel(const float* __restrict__ bh) {
    int idx = blockIdx.x * 256 + threadIdx.x;  // < 49152
    int b = idx / Hx;
    int j = idx - b * Hx;
    float hw[4];
#pragma unroll
    for (int gi = 0; gi < 4; ++gi) {
        int col = j + gi * Hx;
        float v = bh[col];
#pragma unroll
        for (int kc = 0; kc < 6; ++kc)
            v += g_part[((size_t)(kc * Bx + b)) * G4x + col];
        hw[gi] = v;
    }
    float c2 = 0.f;
#pragma unroll 4
    for (int s = Sx - 1; s >= 0; --s) {
        const float* gbp = g_gb + ((size_t)s * Bx + b) * G4x + j;
        float r = fsigm(__ldcs(gbp) + hw[0]);
        float f = fsigm(__ldcs(gbp + Hx) + hw[1]);
        float gg = ftanh(__ldcs(gbp + 2 * Hx) + hw[2]);
        float o = fsigm(__ldcs(gbp + 3 * Hx) + hw[3]);
        c2 = f * c2 + r * gg;
        g_hsb[(size_t)s * (Bx * Hx) + idx] = o * ftanh(c2);
    }
}

// ---------------- 6. output GEMM + pad bias -------------------------------------
__global__ __launch_bounds__(256, 2)
void out_kernel(const float* __restrict__ Wout, const float* __restrict__ bout,
                const int* __restrict__ tokens, float* __restrict__ out) {
    __shared__ float As[64][65];
    __shared__ float Wsm[64][33];
    const int t = threadIdx.x;
    const int rb = blockIdx.x;  // 512
    const int l = t & 31;
    const int rg = t >> 5;  // 0..7
    float acc[8];
#pragma unroll
    for (int i = 0; i < 8; ++i) acc[i] = 0.f;

    for (int kt = 0; kt < 24; ++kt) {
        int k0 = kt * 64;
        const float* src_base = (k0 < Hx) ? g_hsf : g_hsb;
        int koff = (k0 < Hx) ? k0 : (k0 - Hx);
#pragma unroll
        for (int q = 0; q < 4; ++q) {
            int i = t + 256 * q;
            int row = i >> 4;
            int kq = (i & 15) * 4;
            const float* src =
                src_base + ((size_t)(rb * 64 + row)) * Hx + koff + kq;
            float4 v = *(const float4*)src;
            As[row][kq] = v.x; As[row][kq + 1] = v.y;
            As[row][kq + 2] = v.z; As[row][kq + 3] = v.w;
        }
#pragma unroll
        for (int q = 0; q < 2; ++q) {
            int i = t + 256 * q;
            int k = i >> 3;
            int lq = (i & 7) * 4;
            float4 v = *(const float4*)(Wout + (size_t)(k0 + k) * 32 + lq);
            Wsm[k][lq] = v.x; Wsm[k][lq + 1] = v.y;
            Wsm[k][lq + 2] = v.z; Wsm[k][lq + 3] = v.w;
        }
        __syncthreads();
#pragma unroll 8
        for (int k = 0; k < 64; ++k) {
            float w = Wsm[k][l];
#pragma unroll
            for (int i = 0; i < 8; ++i) acc[i] += As[rg * 8 + i][k] * w;
        }
        __syncthreads();
    }
#pragma unroll
    for (int i = 0; i < 8; ++i) {
        int row = rb * 64 + rg * 8 + i;
        float v = acc[i] + bout[l];
        if (l == 0 && tokens[row] == 1) v += 10000.0f;
        out[(size_t)row * 32 + l] = v;
    }
}

// ---------------- launch ---------------------------------------------------------
extern "C" void kernel_launch(void* const* d_in, const int* in_sizes, int n_in,
                              void* d_out, int out_size) {
    (void)in_sizes; (void)n_in; (void)out_size;
    const int* tokens = (const int*)d_in[0];
    const float* embedding = (const float*)d_in[2];
    const float* Wi_f = (const float*)d_in[3];
    const float* bi_f = (const float*)d_in[4];
    const float* Wh_f = (const float*)d_in[5];
    const float* bh_f = (const float*)d_in[6];
    const float* Wi_b = (const float*)d_in[7];
    const float* bi_b = (const float*)d_in[8];
    const float* Wh_b = (const float*)d_in[9];
    const float* bh_b = (const float*)d_in[10];
    const float* Wout = (const float*)d_in[11];
    const float* bout = (const float*)d_in[12];
    float* out = (float*)d_out;

    cudaFuncSetAttribute(fwd_persistent,
                         cudaFuncAttributeMaxDynamicSharedMemorySize, FWD_SMEM);
    cudaFuncSetAttribute(tcw_gemm,
                         cudaFuncAttributeMaxDynamicSharedMemorySize, TCW_SMEM);

    // 1. gather embeddings into compensated bf16 layout [Ah|Al]
    embed_split_kernel<<<SBx * 64 / 256, 256>>>(tokens, embedding);
    // 2. input projections via single uniform bf16 MMA GEMM (K=1536, 3-stage)
    wsplit_kernel<<<dim3(16, 96), 256>>>(Wi_f, 0);
    wsplit_kernel<<<dim3(16, 96), 256>>>(Wi_b, 1);
    tcw_gemm<<<dim3(24, 512), 128, TCW_SMEM>>>(bi_f, 0);
    tcw_gemm<<<dim3(24, 512), 128, TCW_SMEM>>>(bi_b, 1);
    // 3. forward LSTM recurrence (round-13 config + sector-padded flags)
    fwd_persistent<<<NCTA, 256, FWD_SMEM>>>(Wh_f, bh_f);
    // 4. hT @ Wh_b partials
    step_gemm_kernel<<<dim3(24, 6), 256>>>(Wh_b);
    // 5. backward scan
    bscan_kernel<<<192, 256>>>(bh_b);
    // 6. output projection + pad bias
    out_kernel<<<512, 256>>>(Wout, bout, tokens, out);
}

// round 16
// speedup vs baseline: 1.3979x; 1.0222x over previous
#include <cuda_runtime.h>
#include <cuda_bf16.h>
#include <cstdint>

// Problem constants
#define Sx 512
#define Bx 64
#define Ex 512
#define Hx 768
#define G4x 3072
#define SBx 32768      // Sx*Bx
#define KX 1536        // tripled-K for compensated bf16 GEMM (B side)
#define AX 1024        // A side: [Ah | Al] only
#define NCTA 144       // fwd persistent grid (24 nblk x 6 kc)
#define NTHR 36864     // NCTA*256
#define NUNIT 24576    // Bx*Hx/2 gate units (float2)
#define PARTSZ ((size_t)6 * Bx * G4x)  // one partials buffer

// ---------------- scratch (device globals: allocation-guard-safe) -------------
__device__ __nv_bfloat16 g_ax[(size_t)SBx * AX];    // 67 MB   [Ah | Al]
__device__ __nv_bfloat16 g_bxf[(size_t)G4x * KX];   // 9.4 MB  [Bh ; Bh ; Bl] fwd
__device__ __nv_bfloat16 g_bxb[(size_t)G4x * KX];   // 9.4 MB  [Bh ; Bh ; Bl] bwd
__device__ float g_xf[(size_t)SBx * G4x];    // 402 MB  emb@Wi_f + bi_f     [SB,4H]
__device__ float g_gb[(size_t)SBx * G4x];    // 402 MB  emb@Wi_b + bi_b     [SB,4H]
__device__ float g_hsf[(size_t)SBx * Hx];    // 100 MB  forward hiddens     [S,B,H]
__device__ float g_hsb[(size_t)SBx * Hx];    // 100 MB  backward hiddens    [S,B,H]
__device__ float g_part[2 * PARTSZ];         // 9.4 MB  double-buffered partials
__device__ uint32_t g_hhi[NUNIT];            // current hidden hi (bf16x2)
__device__ uint32_t g_hlo[NUNIT];            // current hidden lo (bf16x2)
__device__ unsigned int g_flags[NCTA];       // global barrier per-CTA gen (packed)
__device__ unsigned int g_gflags[NCTA * 8];  // group barrier per-CTA gen (stride 8)
__device__ unsigned int g_ggen[6 * 32];      // per-group broadcast (128B apart)
__device__ unsigned int g_bar_gen;           // global broadcast generation

// ---------------- f32x2 helpers (for step_gemm one-shot) -----------------------
__device__ __forceinline__ void fma2(unsigned long long& d, unsigned long long a,
                                     unsigned long long b) {
    asm("fma.rn.f32x2 %0, %1, %2, %0;" : "+l"(d) : "l"(a), "l"(b));
}
__device__ __forceinline__ unsigned long long pack2(float x) {
    unsigned long long r;
    asm("mov.b64 %0, {%1, %1};" : "=l"(r) : "f"(x));
    return r;
}
__device__ __forceinline__ float2 unpack2(unsigned long long v) {
    float2 f;
    asm("mov.b64 {%0, %1}, %2;" : "=f"(f.x), "=f"(f.y) : "l"(v));
    return f;
}

// ---------------- fast transcendentals (MUFU, rel err ~3e-7) -------------------
__device__ __forceinline__ float fsigm(float x) {
    float t, r;
    asm("ex2.approx.f32 %0, %1;" : "=f"(t) : "f"(-1.4426950408889634f * x));
    asm("rcp.approx.f32 %0, %1;" : "=f"(r) : "f"(1.0f + t));
    return r;
}
__device__ __forceinline__ float ftanh(float x) {
    return fmaf(2.0f, fsigm(2.0f * x), -1.0f);
}

// ---------------- misc helpers --------------------------------------------------
__device__ __forceinline__ uint32_t smem_u32(const void* p) {
    uint32_t a;
    asm("{ .reg .u64 t; cvta.to.shared.u64 t, %1; cvt.u32.u64 %0, t; }"
        : "=r"(a) : "l"(p));
    return a;
}
__device__ __forceinline__ void st_rel(unsigned int* p, unsigned int v) {
    asm volatile("st.release.gpu.global.u32 [%0], %1;" :: "l"(p), "r"(v) : "memory");
}
__device__ __forceinline__ unsigned int ld_acq(const unsigned int* p) {
    unsigned int v;
    asm volatile("ld.acquire.gpu.global.u32 %0, [%1];" : "=r"(v) : "l"(p) : "memory");
    return v;
}

// global grid barrier: per-CTA packed flag release; CTA0 aggregates (1 thread
// per flag) and broadcasts; other CTAs poll the broadcast word with 1 thread.
__device__ __forceinline__ void gsync(unsigned int& gen) {
    __syncthreads();
    gen++;
    if (threadIdx.x == 0) {
        st_rel(&g_flags[blockIdx.x], gen);  // release orders prior writes
    }
    if (blockIdx.x == 0) {
        if (threadIdx.x < NCTA) {
            while ((int)(ld_acq(&g_flags[threadIdx.x]) - gen) < 0) {}
        }
        __syncthreads();
        if (threadIdx.x == 0) st_rel(&g_bar_gen, gen);
    } else {
        if (threadIdx.x == 0) {
            while ((int)(ld_acq(&g_bar_gen) - gen) < 0) {}
        }
    }
    __syncthreads();
}

// group barrier (24 CTAs of group kc) via per-group aggregator:
// leader (nblk==0) polls 24 flags (1 thread each), releases the group word;
// followers poll the group word with 1 thread. Fan-in: 1 poller/flag.
__device__ __forceinline__ void gsync_group(unsigned int& ggen, int kc, int nblk) {
    __syncthreads();
    ggen++;
    if (threadIdx.x == 0) {
        st_rel(&g_gflags[blockIdx.x * 8], ggen);  // release orders prior writes
    }
    if (nblk == 0) {
        if (threadIdx.x < 24) {
            const unsigned int* f = &g_gflags[(kc * 24 + threadIdx.x) * 8];
            while ((int)(ld_acq(f) - ggen) < 0) {}
        }
        __syncthreads();
        if (threadIdx.x == 0) st_rel(&g_ggen[kc * 32], ggen);
    } else {
        if (threadIdx.x == 0) {
            while ((int)(ld_acq(&g_ggen[kc * 32]) - ggen) < 0) {}
        }
    }
    __syncthreads();
}

// ---------------- mma.sync / ldmatrix / cp.async macros -------------------------
#define LDSM4(r, addr) \
    asm volatile("ldmatrix.sync.aligned.m8n8.x4.shared.b16 {%0,%1,%2,%3}, [%4];" \
                 : "=r"((r)[0]), "=r"((r)[1]), "=r"((r)[2]), "=r"((r)[3]) \
                 : "r"(addr))
#define MMA16816(c, a, b0v, b1v) \
    asm volatile("mma.sync.aligned.m16n8k16.row.col.f32.bf16.bf16.f32 " \
                 "{%0,%1,%2,%3}, {%4,%5,%6,%7}, {%8,%9}, {%0,%1,%2,%3};" \
                 : "+f"((c)[0]), "+f"((c)[1]), "+f"((c)[2]), "+f"((c)[3]) \
                 : "r"((a)[0]), "r"((a)[1]), "r"((a)[2]), "r"((a)[3]), \
                   "r"(b0v), "r"(b1v))
__device__ __forceinline__ void cp16(uint32_t dst, const void* src) {
    asm volatile("cp.async.cg.shared.global [%0], [%1], 16;"
                 :: "r"(dst), "l"(src));
}
#define CP_COMMIT() asm volatile("cp.async.commit_group;" ::: "memory")
#define CP_WAIT(n) asm volatile("cp.async.wait_group %0;" :: "n"(n) : "memory")
__device__ __forceinline__ void sst16(uint32_t addr, unsigned short v) {
    asm volatile("st.shared.b16 [%0], %1;" :: "r"(addr), "h"(v));
}

// ---------------- 1. embedding gather + compensated layout ---------------------
__device__ __forceinline__ uint32_t packbf2(float a, float b) {
    __nv_bfloat162 t = __floats2bfloat162_rn(a, b);
    return *(uint32_t*)&t;
}
__global__ void embed_split_kernel(const int* __restrict__ tokens,
                                   const float* __restrict__ embedding) {
    int idx = blockIdx.x * blockDim.x + threadIdx.x;  // over SB * 64 (8 elems each)
    int e8 = idx & 63;
    int sb = idx >> 6;
    int tok = tokens[sb];
    const float4* src = (const float4*)(embedding + (size_t)tok * Ex + e8 * 8);
    float4 v0 = src[0], v1 = src[1];
    float hv[8], lo[8];
    float in[8] = {v0.x, v0.y, v0.z, v0.w, v1.x, v1.y, v1.z, v1.w};
#pragma unroll
    for (int i = 0; i < 8; ++i) {
        hv[i] = __bfloat162float(__float2bfloat16_rn(in[i]));
        lo[i] = in[i] - hv[i];
    }
    uint4 ph, pl;
    ph.x = packbf2(in[0], in[1]); ph.y = packbf2(in[2], in[3]);
    ph.z = packbf2(in[4], in[5]); ph.w = packbf2(in[6], in[7]);
    pl.x = packbf2(lo[0], lo[1]); pl.y = packbf2(lo[2], lo[3]);
    pl.z = packbf2(lo[4], lo[5]); pl.w = packbf2(lo[6], lo[7]);
    size_t off = (size_t)sb * AX + e8 * 8;
    *(uint4*)(g_ax + off) = ph;
    *(uint4*)(g_ax + off + 512) = pl;
}

// ---------------- 1b. W transpose + compensated layout --------------------------
__global__ void wsplit_kernel(const float* __restrict__ W, int which) {
    __shared__ float tile[32][33];
    __nv_bfloat16* dst = which ? g_bxb : g_bxf;
    const int kb = blockIdx.x;  // 16
    const int nb = blockIdx.y;  // 96
    const int t = threadIdx.x;
    const int c = t & 31;
    const int r0 = t >> 5;  // 0..7
#pragma unroll
    for (int q = 0; q < 4; ++q) {
        int r = r0 + 8 * q;
        tile[r][c] = W[(size_t)(kb * 32 + r) * G4x + nb * 32 + c];
    }
    __syncthreads();
#pragma unroll
    for (int q = 0; q < 4; ++q) {
        int i = r0 + 8 * q;            // n within tile
        float v = tile[c][i];          // W[kb*32+c][nb*32+i]
        __nv_bfloat16 hb = __float2bfloat16_rn(v);
        float hvf = __bfloat162float(hb);
        size_t off = (size_t)(nb * 32 + i) * KX + kb * 32 + c;
        dst[off] = hb;
        dst[off + 512] = hb;
        dst[off + 1024] = __float2bfloat16_rn(v - hvf);
    }
}

// ---------------- 2. warp-MMA input GEMM (uniform bf16, K=1536, 3-stage) --------
#define TCW_STAGE 24576                 // A 8KB + B 16KB
#define TCW_SMEM (3 * TCW_STAGE)        // 72 KB

__device__ __forceinline__ void load_tileA64(const __nv_bfloat16* __restrict__ g,
                                             uint32_t sbase, int blk, int t) {
    int aoff = (blk < 16 ? blk : blk - 16) * 128;  // byte offset in 2048B row
#pragma unroll
    for (int q = 0; q < 4; ++q) {
        int idx = t + 128 * q;         // < 512 : 64 rows x 8 chunks
        int r = idx >> 3, c = idx & 7;
        const char* src = (const char*)g + (size_t)r * (AX * 2) + aoff + c * 16;
        uint32_t dst = sbase + r * 128 + ((c ^ (r & 7)) << 4);
        cp16(dst, src);
    }
}
__device__ __forceinline__ void load_tileB128(const __nv_bfloat16* __restrict__ g,
                                              uint32_t sbase, int blk, int t) {
#pragma unroll
    for (int q = 0; q < 8; ++q) {
        int idx = t + 128 * q;         // < 1024 : 128 rows x 8 chunks
        int r = idx >> 3, c = idx & 7;
        const char* src = (const char*)g + (size_t)r * (KX * 2) + blk * 128 + c * 16;
        uint32_t dst = sbase + r * 128 + ((c ^ (r & 7)) << 4);
        cp16(dst, src);
    }
}

__global__ __launch_bounds__(128, 2)
void tcw_gemm(const float* __restrict__ bias, int which) {
    extern __shared__ char smraw[];
    uint32_t smb = smem_u32(smraw);
    const int t = threadIdx.x;
    const int l = t & 31;
    const int wid = t >> 5;            // 0..3
    const int nblk = blockIdx.x;       // 24
    const int mblk = blockIdx.y;       // 512 (rows of 64)

    const __nv_bfloat16* Ag = g_ax + (size_t)mblk * 64 * AX;
    const __nv_bfloat16* Bg = (which ? g_bxb : g_bxf) + (size_t)nblk * 128 * KX;
    float* out = which ? g_gb : g_xf;

    float acc[2][8][4];
#pragma unroll
    for (int i = 0; i < 2; ++i)
#pragma unroll
        for (int j = 0; j < 8; ++j)
#pragma unroll
            for (int q = 0; q < 4; ++q) acc[i][j][q] = 0.0f;

    const int warp_m0 = (wid & 1) * 32;
    const int warp_n0 = (wid >> 1) * 64;
    const int ar = warp_m0 + (l & 15);
    const int ac_hi = l >> 4;
    const int br = warp_n0 + (l & 7) + ((l >> 4) << 3);
    const int bc_hi = (l >> 3) & 1;

    // prologue: stages 0,1
#pragma unroll
    for (int p = 0; p < 2; ++p) {
        uint32_t b0 = smb + p * TCW_STAGE;
        load_tileA64(Ag, b0, p, t);
        load_tileB128(Bg, b0 + 8192, p, t);
        CP_COMMIT();
    }

    int st_r = 0, st_w = 2;
    for (int blk = 0; blk < 24; ++blk) {
        if (blk < 22) {
            uint32_t nb = smb + st_w * TCW_STAGE;
            load_tileA64(Ag, nb, blk + 2, t);
            load_tileB128(Bg, nb + 8192, blk + 2, t);
            CP_COMMIT();
            st_w = (st_w == 2) ? 0 : st_w + 1;
        }
        if (blk <= 21) CP_WAIT(2);
        else if (blk == 22) CP_WAIT(1);
        else CP_WAIT(0);
        __syncthreads();

        uint32_t AB = smb + st_r * TCW_STAGE;
        uint32_t BB = AB + 8192;
#pragma unroll
        for (int ks = 0; ks < 4; ++ks) {
            uint32_t a_r[2][4];
#pragma unroll
            for (int mt = 0; mt < 2; ++mt) {
                int r = ar + mt * 16;
                int c = ks * 2 + ac_hi;
                LDSM4(a_r[mt], AB + r * 128 + ((c ^ (r & 7)) << 4));
            }
            uint32_t b_r[4][4];
#pragma unroll
            for (int np = 0; np < 4; ++np) {
                int r = br + np * 16;
                int c = ks * 2 + bc_hi;
                LDSM4(b_r[np], BB + r * 128 + ((c ^ (r & 7)) << 4));
            }
#pragma unroll
            for (int mt = 0; mt < 2; ++mt)
#pragma unroll
                for (int np = 0; np < 4; ++np)
#pragma unroll
                    for (int hf = 0; hf < 2; ++hf)
                        MMA16816(acc[mt][np * 2 + hf], a_r[mt],
                                 b_r[np][hf * 2], b_r[np][hf * 2 + 1]);
        }
        __syncthreads();
        st_r = (st_r == 2) ? 0 : st_r + 1;
    }

    const int row0 = mblk * 64 + warp_m0 + (l >> 2);
    const int col0 = nblk * 128 + warp_n0 + (l & 3) * 2;
#pragma unroll
    for (int mt = 0; mt < 2; ++mt) {
#pragma unroll
        for (int nt = 0; nt < 8; ++nt) {
            int rr = row0 + mt * 16;
            int cc = col0 + nt * 8;
            float2 bv = *(const float2*)(bias + cc);
            float2 o0, o1;
            o0.x = acc[mt][nt][0] + bv.x;
            o0.y = acc[mt][nt][1] + bv.y;
            o1.x = acc[mt][nt][2] + bv.x;
            o1.y = acc[mt][nt][3] + bv.y;
            *(float2*)(out + (size_t)rr * G4x + cc) = o0;
            *(float2*)(out + (size_t)(rr + 8) * G4x + cc) = o1;
        }
    }
}

// ---------------- 3. persistent forward recurrence ------------------------------
// dedup smem (96 KB, occ 1) + kc-local gates + per-group aggregated barrier.
// Per step: [cp.async h | GEMM | part write (parity s&1) | GLOBAL barrier |
//            gates (own kc slice units; read all-kc partials, parity s&1) |
//            GROUP barrier (24 CTAs, aggregator topology)].
#define FWD_SMEM 98304
#define HP2 512

__device__ __forceinline__ uint32_t swadr2(uint32_t base, int r, int chunk) {
    return base + r * HP2 + ((chunk ^ (r & 7)) << 4);
}

__global__ __launch_bounds__(256, 1)
void fwd_persistent(const float* __restrict__ Wh, const float* __restrict__ bh) {
    extern __shared__ char smraw[];
    const uint32_t HB = smem_u32(smraw);
    const uint32_t WB = HB + 32768;

    const int t = threadIdx.x;
    const int l = t & 31;
    const int wid = t >> 5;
    const int bid = blockIdx.x;
    const int nblk = bid % 24;
    const int kc = bid / 24;
    unsigned int gen = ld_acq(&g_bar_gen);           // monotonic seed (global)
    unsigned int ggen = ld_acq(&g_gflags[bid * 8]);  // monotonic seed (group)

    // zero hidden hi/lo
    for (int i = bid * 256 + t; i < NUNIT; i += NTHR) {
        __stcg(&g_hhi[i], 0u);
        __stcg(&g_hlo[i], 0u);
    }

    // one-time W tile split: Wsm[n][hi|lo] from Wh[kc*128+k][nblk*128+n]
    for (int idx = t; idx < 128 * 128; idx += 256) {
        int n = idx & 127;
        int k = idx >> 7;
        float v = Wh[(size_t)(kc * 128 + k) * G4x + nblk * 128 + n];
        __nv_bfloat16 hb = __float2bfloat16_rn(v);
        float hvf = __bfloat162float(hb);
        __nv_bfloat16 lb = __float2bfloat16_rn(v - hvf);
        int ch = k >> 3, in8 = (k & 7) << 1;
        sst16(swadr2(WB, n, ch) + in8, *(unsigned short*)&hb);
        sst16(swadr2(WB, n, 16 + ch) + in8, *(unsigned short*)&lb);
    }

    // gates: kc-local units. Group kc owns 4096 units (64 b x 64 j-slice);
    // CTA nblk takes a contiguous range of 170-171.
    const int gstart = (4096 * nblk) / 24;
    const int gend = (4096 * (nblk + 1)) / 24;
    const int gidx = gstart + t;
    const bool act = (t < gend - gstart);
    int gb = 0, gj = 0, u = 0;
    float2 bh2[4];
    float c0 = 0.0f, c1 = 0.0f;
    if (act) {
        gb = gidx >> 6;                  // b in 0..63
        int jo = gidx & 63;              // j offset within kc slice
        int j = kc * 64 + jo;            // unit j in 0..383
        u = gb * 384 + j;                // g_hhi/g_hlo unit index
        gj = j * 2;                      // element offset within H row
#pragma unroll
        for (int gi = 0; gi < 4; ++gi)
            bh2[gi] = *(const float2*)(bh + gj + gi * Hx);
    }

    // mma addressing: 8 warps = 2 m-groups x 4 n-groups
    const int mg = wid >> 2;
    const int ng = wid & 3;
    const int ar_ = mg * 32 + (l & 15);
    const int ac_hi = l >> 4;
    const int br_ = ng * 32 + (l & 7) + ((l >> 4) << 3);
    const int bc_hi = (l >> 3) & 1;

    // prefetch xf for s=0
    float2 xf2[4];
    if (act) {
        const float* xfp = g_xf + (size_t)gb * G4x + gj;
#pragma unroll
        for (int gi = 0; gi < 4; ++gi)
            xf2[gi] = __ldcs((const float2*)(xfp + gi * Hx));
    }

    gsync(gen);  // W tile + zeroed h visible everywhere

    for (int s = 0; s < Sx; ++s) {
        const size_t pb = (size_t)(s & 1) * PARTSZ;

        // cp.async h tiles: [hi | lo] from g_hhi/g_hlo (bf16 pairs), 32 KB
#pragma unroll
        for (int q = 0; q < 8; ++q) {
            int idx2 = t + 256 * (q & 3);  // < 1024
            int region = q >> 2;           // 0:hi 1:lo
            int b = idx2 >> 4, c16 = idx2 & 15;
            const char* src =
                (const char*)(region ? g_hlo : g_hhi) + b * 1536 +
                kc * 256 + c16 * 16;
            cp16(swadr2(HB, b, region * 16 + c16), src);
        }
        CP_COMMIT();
        CP_WAIT(0);
        __syncthreads();

        // mma GEMM: per k16-chunk load 4 fragment sets, 3 products each
        float acc[2][4][4];
#pragma unroll
        for (int i = 0; i < 2; ++i)
#pragma unroll
            for (int j = 0; j < 4; ++j)
#pragma unroll
                for (int q = 0; q < 4; ++q) acc[i][j][q] = 0.0f;

#pragma unroll
        for (int c8 = 0; c8 < 8; ++c8) {
            uint32_t aH[2][4], aL[2][4];
#pragma unroll
            for (int mt = 0; mt < 2; ++mt) {
                int r = ar_ + mt * 16;
                int cH = c8 * 2 + ac_hi;
                int cL = (8 + c8) * 2 + ac_hi;
                LDSM4(aH[mt], HB + r * HP2 + ((cH ^ (r & 7)) << 4));
                LDSM4(aL[mt], HB + r * HP2 + ((cL ^ (r & 7)) << 4));
            }
            uint32_t bH[2][4], bL[2][4];
#pragma unroll
            for (int np = 0; np < 2; ++np) {
                int r = br_ + np * 16;
                int cH = c8 * 2 + bc_hi;
                int cL = (8 + c8) * 2 + bc_hi;
                LDSM4(bH[np], WB + r * HP2 + ((cH ^ (r & 7)) << 4));
                LDSM4(bL[np], WB + r * HP2 + ((cL ^ (r & 7)) << 4));
            }
#pragma unroll
            for (int mt = 0; mt < 2; ++mt) {
#pragma unroll
                for (int np = 0; np < 2; ++np) {
#pragma unroll
                    for (int hf = 0; hf < 2; ++hf) {
                        int nt = np * 2 + hf;
                        MMA16816(acc[mt][nt], aH[mt], bH[np][hf * 2],
                                 bH[np][hf * 2 + 1]);
                        MMA16816(acc[mt][nt], aL[mt], bH[np][hf * 2],
                                 bH[np][hf * 2 + 1]);
                        MMA16816(acc[mt][nt], aH[mt], bL[np][hf * 2],
                                 bL[np][hf * 2 + 1]);
                    }
                }
            }
        }

        // epilogue -> g_part[pb][kc][b][n] (L2-coherent)
        {
            const int row0 = mg * 32 + (l >> 2);
            const int col0 = nblk * 128 + ng * 32 + (l & 3) * 2;
#pragma unroll
            for (int mt = 0; mt < 2; ++mt) {
#pragma unroll
                for (int nt = 0; nt < 4; ++nt) {
                    int b = row0 + mt * 16;
                    int n = col0 + nt * 8;
                    float2 v0 = {acc[mt][nt][0], acc[mt][nt][1]};
                    float2 v1 = {acc[mt][nt][2], acc[mt][nt][3]};
                    __stcg((float2*)(g_part + pb +
                                     ((size_t)(kc * Bx + b)) * G4x + n), v0);
                    __stcg((float2*)(g_part + pb +
                                     ((size_t)(kc * Bx + b + 8)) * G4x + n), v1);
                }
            }
        }
        gsync(gen);  // all partials of step s visible

        // gates (kc-local units; MUFU transcendentals)
        if (act) {
            float g0[4], g1[4];
#pragma unroll
            for (int gi = 0; gi < 4; ++gi) {
                float v0 = xf2[gi].x + bh2[gi].x;
                float v1 = xf2[gi].y + bh2[gi].y;
                const float* pp = g_part + pb + (size_t)gb * G4x + gj + gi * Hx;
#pragma unroll
                for (int kcc = 0; kcc < 6; ++kcc) {
                    float2 pv = __ldcg((const float2*)(pp + (size_t)kcc *
                                                       (Bx * G4x)));
                    v0 += pv.x;
                    v1 += pv.y;
                }
                g0[gi] = v0;
                g1[gi] = v1;
            }
            float r0 = fsigm(g0[0]), f0 = fsigm(g0[1]);
            float t0 = ftanh(g0[2]), o0 = fsigm(g0[3]);
            float r1 = fsigm(g1[0]), f1 = fsigm(g1[1]);
            float t1 = ftanh(g1[2]), o1 = fsigm(g1[3]);
            c0 = f0 * c0 + r0 * t0;
            c1 = f1 * c1 + r1 * t1;
            float h0 = o0 * ftanh(c0);
            float h1 = o1 * ftanh(c1);
            float2 h2 = {h0, h1};
            *(float2*)(g_hsf + (size_t)s * (Bx * Hx) + gb * Hx + gj) = h2;
            float hr0 = __bfloat162float(__float2bfloat16_rn(h0));
            float hr1 = __bfloat162float(__float2bfloat16_rn(h1));
            __stcg(&g_hhi[u], packbf2(h0, h1));
            __stcg(&g_hlo[u], packbf2(h0 - hr0, h1 - hr1));
            // prefetch xf for next step (independent of the barrier below)
            if (s + 1 < Sx) {
                const float* xfp = g_xf + ((size_t)(s + 1) * Bx + gb) * G4x + gj;
#pragma unroll
                for (int gi = 0; gi < 4; ++gi)
                    xf2[gi] = __ldcs((const float2*)(xfp + gi * Hx));
            }
        }
        gsync_group(ggen, kc, nblk);  // our kc h-slice ready (group-written)
    }
}

// ---------------- 4. one-shot hidden GEMM for hT @ Wh_b (split-K partials) ----
__global__ __launch_bounds__(256, 2)
void step_gemm_kernel(const float* __restrict__ Wh) {
    __shared__ float hsT[16][68];
    __shared__ float Wsm[16][128];
    const float* hsrc = g_hsf + (size_t)(Sx - 1) * Bx * Hx;  // hT = hsf[511]
    const int t = threadIdx.x;
    const int nblk = blockIdx.x;  // 24
    const int kc = blockIdx.y;    // 6
    const float* Wb = Wh + nblk * 128;

    unsigned long long acc[4][4];
#pragma unroll
    for (int i = 0; i < 4; ++i)
#pragma unroll
        for (int j = 0; j < 4; ++j) acc[i][j] = 0ull;

    const int la_b = t >> 2;
    const int la_k = (t & 3) * 4;
    const int lb_k = t >> 5;
    const int lb_n = (t & 31) * 4;
    const int b0 = (t >> 4) * 4;
    const int n0 = (t & 15) * 8;

    for (int kt = 0; kt < 8; ++kt) {
        int k0 = kc * 128 + kt * 16;
        float4 va = *(const float4*)(hsrc + la_b * Hx + k0 + la_k);
        float4 vb0 = *(const float4*)(Wb + (size_t)(k0 + lb_k) * G4x + lb_n);
        float4 vb1 = *(const float4*)(Wb + (size_t)(k0 + lb_k + 8) * G4x + lb_n);
        hsT[la_k + 0][la_b] = va.x; hsT[la_k + 1][la_b] = va.y;
        hsT[la_k + 2][la_b] = va.z; hsT[la_k + 3][la_b] = va.w;
        *(float4*)(&Wsm[lb_k][lb_n]) = vb0;
        *(float4*)(&Wsm[lb_k + 8][lb_n]) = vb1;
        __syncthreads();
#pragma unroll
        for (int k = 0; k < 16; ++k) {
            float a[4];
            *(float4*)a = *(const float4*)(&hsT[k][b0]);
            ulonglong2 b01 = *(const ulonglong2*)(&Wsm[k][n0]);
            ulonglong2 b23 = *(const ulonglong2*)(&Wsm[k][n0 + 4]);
            unsigned long long bb0 = b01.x, bb1 = b01.y, bb2 = b23.x, bb3 = b23.y;
#pragma unroll
            for (int i = 0; i < 4; ++i) {
                unsigned long long a2 = pack2(a[i]);
                fma2(acc[i][0], a2, bb0);
                fma2(acc[i][1], a2, bb1);
                fma2(acc[i][2], a2, bb2);
                fma2(acc[i][3], a2, bb3);
            }
        }
        __syncthreads();
    }
#pragma unroll
    for (int i = 0; i < 4; ++i) {
#pragma unroll
        for (int j = 0; j < 4; ++j) {
            float2 v = unpack2(acc[i][j]);
            int gn = nblk * 128 + n0 + j * 2;
            *(float2*)(g_part + ((size_t)(kc * Bx + b0 + i)) * G4x + gn) = v;
        }
    }
}

// ---------------- 5. backward (constant-hT) scan --------------------------------
__global__ void bscan_kernel(const float* __restrict__ bh) {
    int idx = blockIdx.x * 256 + threadIdx.x;  // < 49152
    int b = idx / Hx;
    int j = idx - b * Hx;
    float hw[4];
#pragma unroll
    for (int gi = 0; gi < 4; ++gi) {
        int col = j + gi * Hx;
        float v = bh[col];
#pragma unroll
        for (int kc = 0; kc < 6; ++kc)
            v += g_part[((size_t)(kc * Bx + b)) * G4x + col];
        hw[gi] = v;
    }
    float c2 = 0.f;
#pragma unroll 4
    for (int s = Sx - 1; s >= 0; --s) {
        const float* gbp = g_gb + ((size_t)s * Bx + b) * G4x + j;
        float r = fsigm(__ldcs(gbp) + hw[0]);
        float f = fsigm(__ldcs(gbp + Hx) + hw[1]);
        float gg = ftanh(__ldcs(gbp + 2 * Hx) + hw[2]);
        float o = fsigm(__ldcs(gbp + 3 * Hx) + hw[3]);
        c2 = f * c2 + r * gg;
        g_hsb[(size_t)s * (Bx * Hx) + idx] = o * ftanh(c2);
    }
}

// ---------------- 6. output GEMM + pad bias -------------------------------------
__global__ __launch_bounds__(256, 2)
void out_kernel(const float* __restrict__ Wout, const float* __restrict__ bout,
                const int* __restrict__ tokens, float* __restrict__ out) {
    __shared__ float As[64][65];
    __shared__ float Wsm[64][33];
    const int t = threadIdx.x;
    const int rb = blockIdx.x;  // 512
    const int l = t & 31;
    const int rg = t >> 5;  // 0..7
    float acc[8];
#pragma unroll
    for (int i = 0; i < 8; ++i) acc[i] = 0.f;

    for (int kt = 0; kt < 24; ++kt) {
        int k0 = kt * 64;
        const float* src_base = (k0 < Hx) ? g_hsf : g_hsb;
        int koff = (k0 < Hx) ? k0 : (k0 - Hx);
#pragma unroll
        for (int q = 0; q < 4; ++q) {
            int i = t + 256 * q;
            int row = i >> 4;
            int kq = (i & 15) * 4;
            const float* src =
                src_base + ((size_t)(rb * 64 + row)) * Hx + koff + kq;
            float4 v = *(const float4*)src;
            As[row][kq] = v.x; As[row][kq + 1] = v.y;
            As[row][kq + 2] = v.z; As[row][kq + 3] = v.w;
        }
#pragma unroll
        for (int q = 0; q < 2; ++q) {
            int i = t + 256 * q;
            int k = i >> 3;
            int lq = (i & 7) * 4;
            float4 v = *(const float4*)(Wout + (size_t)(k0 + k) * 32 + lq);
            Wsm[k][lq] = v.x; Wsm[k][lq + 1] = v.y;
            Wsm[k][lq + 2] = v.z; Wsm[k][lq + 3] = v.w;
        }
        __syncthreads();
#pragma unroll 8
        for (int k = 0; k < 64; ++k) {
            float w = Wsm[k][l];
#pragma unroll
            for (int i = 0; i < 8; ++i) acc[i] += As[rg * 8 + i][k] * w;
        }
        __syncthreads();
    }
#pragma unroll
    for (int i = 0; i < 8; ++i) {
        int row = rb * 64 + rg * 8 + i;
        float v = acc[i] + bout[l];
        if (l == 0 && tokens[row] == 1) v += 10000.0f;
        out[(size_t)row * 32 + l] = v;
    }
}

// ---------------- launch ---------------------------------------------------------
extern "C" void kernel_launch(void* const* d_in, const int* in_sizes, int n_in,
                              void* d_out, int out_size) {
    (void)in_sizes; (void)n_in; (void)out_size;
    const int* tokens = (const int*)d_in[0];
    const float* embedding = (const float*)d_in[2];
    const float* Wi_f = (const float*)d_in[3];
    const float* bi_f = (const float*)d_in[4];
    const float* Wh_f = (const float*)d_in[5];
    const float* bh_f = (const float*)d_in[6];
    const float* Wi_b = (const float*)d_in[7];
    const float* bi_b = (const float*)d_in[8];
    const float* Wh_b = (const float*)d_in[9];
    const float* bh_b = (const float*)d_in[10];
    const float* Wout = (const float*)d_in[11];
    const float* bout = (const float*)d_in[12];
    float* out = (float*)d_out;

    cudaFuncSetAttribute(fwd_persistent,
                         cudaFuncAttributeMaxDynamicSharedMemorySize, FWD_SMEM);
    cudaFuncSetAttribute(tcw_gemm,
                         cudaFuncAttributeMaxDynamicSharedMemorySize, TCW_SMEM);

    // 1. gather embeddings into compensated bf16 layout [Ah|Al]
    embed_split_kernel<<<SBx * 64 / 256, 256>>>(tokens, embedding);
    // 2. input projections via single uniform bf16 MMA GEMM (K=1536, 3-stage)
    wsplit_kernel<<<dim3(16, 96), 256>>>(Wi_f, 0);
    wsplit_kernel<<<dim3(16, 96), 256>>>(Wi_b, 1);
    tcw_gemm<<<dim3(24, 512), 128, TCW_SMEM>>>(bi_f, 0);
    tcw_gemm<<<dim3(24, 512), 128, TCW_SMEM>>>(bi_b, 1);
    // 3. forward LSTM recurrence (kc-local gates + aggregated group barrier)
    fwd_persistent<<<NCTA, 256, FWD_SMEM>>>(Wh_f, bh_f);
    // 4. hT @ Wh_b partials
    step_gemm_kernel<<<dim3(24, 6), 256>>>(Wh_b);
    // 5. backward scan
    bscan_kernel<<<192, 256>>>(bh_b);
    // 6. output projection + pad bias
    out_kernel<<<512, 256>>>(Wout, bout, tokens, out);
}

// round 17
// speedup vs baseline: 1.4656x; 1.0484x over previous
#include <cuda_runtime.h>
#include <cuda_bf16.h>
#include <cstdint>

// Problem constants
#define Sx 512
#define Bx 64
#define Ex 512
#define Hx 768
#define G4x 3072
#define SBx 32768      // Sx*Bx
#define KX 1536        // tripled-K for compensated bf16 GEMM (B side)
#define AX 1024        // A side: [Ah | Al] only
#define NCTA 144       // fwd persistent grid (24 nblk x 6 kc)
#define NTHR 36864     // NCTA*256
#define NUNIT 24576    // Bx*Hx/2 gate units (float2)

// ---------------- scratch (device globals: allocation-guard-safe) -------------
__device__ __nv_bfloat16 g_ax[(size_t)SBx * AX];    // 67 MB   [Ah | Al]
__device__ __nv_bfloat16 g_bxf[(size_t)G4x * KX];   // 9.4 MB  [Bh ; Bh ; Bl] fwd
__device__ __nv_bfloat16 g_bxb[(size_t)G4x * KX];   // 9.4 MB  [Bh ; Bh ; Bl] bwd
__device__ float g_xf[(size_t)SBx * G4x];    // 402 MB  emb@Wi_f + bi_f     [SB,4H]
__device__ float g_gb[(size_t)SBx * G4x];    // 402 MB  emb@Wi_b + bi_b     [SB,4H]
__device__ float g_hsf[(size_t)SBx * Hx];    // 100 MB  forward hiddens     [S,B,H]
__device__ float g_hsb[(size_t)SBx * Hx];    // 100 MB  backward hiddens    [S,B,H]
__device__ float g_part[6 * Bx * G4x];       // 4.7 MB  split-K partials [6,B,4H]
__device__ uint32_t g_hhi[NUNIT];            // current hidden hi (bf16x2)
__device__ uint32_t g_hlo[NUNIT];            // current hidden lo (bf16x2)
__device__ unsigned int g_flags[NCTA];       // per-CTA barrier generation
__device__ unsigned int g_bar_gen;           // broadcast generation

// ---------------- f32x2 helpers (for step_gemm one-shot) -----------------------
__device__ __forceinline__ void fma2(unsigned long long& d, unsigned long long a,
                                     unsigned long long b) {
    asm("fma.rn.f32x2 %0, %1, %2, %0;" : "+l"(d) : "l"(a), "l"(b));
}
__device__ __forceinline__ unsigned long long pack2(float x) {
    unsigned long long r;
    asm("mov.b64 %0, {%1, %1};" : "=l"(r) : "f"(x));
    return r;
}
__device__ __forceinline__ float2 unpack2(unsigned long long v) {
    float2 f;
    asm("mov.b64 {%0, %1}, %2;" : "=f"(f.x), "=f"(f.y) : "l"(v));
    return f;
}

// ---------------- fast transcendentals (MUFU, rel err ~3e-7) -------------------
__device__ __forceinline__ float fsigm(float x) {
    float t, r;
    asm("ex2.approx.f32 %0, %1;" : "=f"(t) : "f"(-1.4426950408889634f * x));
    asm("rcp.approx.f32 %0, %1;" : "=f"(r) : "f"(1.0f + t));
    return r;
}
__device__ __forceinline__ float ftanh(float x) {
    return fmaf(2.0f, fsigm(2.0f * x), -1.0f);
}

// ---------------- misc helpers --------------------------------------------------
__device__ __forceinline__ uint32_t smem_u32(const void* p) {
    uint32_t a;
    asm("{ .reg .u64 t; cvta.to.shared.u64 t, %1; cvt.u32.u64 %0, t; }"
        : "=r"(a) : "l"(p));
    return a;
}
__device__ __forceinline__ void st_rel(unsigned int* p, unsigned int v) {
    asm volatile("st.release.gpu.global.u32 [%0], %1;" :: "l"(p), "r"(v) : "memory");
}
__device__ __forceinline__ unsigned int ld_acq(const unsigned int* p) {
    unsigned int v;
    asm volatile("ld.acquire.gpu.global.u32 %0, [%1];" : "=r"(v) : "l"(p) : "memory");
    return v;
}

// grid barrier: per-CTA flag release; CTA0 aggregates (1 thread per flag) and
// broadcasts; other CTAs poll the broadcast word with 1 thread each.
__device__ __forceinline__ void gsync(unsigned int& gen) {
    __syncthreads();
    gen++;
    if (threadIdx.x == 0) {
        st_rel(&g_flags[blockIdx.x], gen);  // release orders prior writes
    }
    if (blockIdx.x == 0) {
        if (threadIdx.x < NCTA) {
            while ((int)(ld_acq(&g_flags[threadIdx.x]) - gen) < 0) {}
        }
        __syncthreads();
        if (threadIdx.x == 0) st_rel(&g_bar_gen, gen);
    } else {
        if (threadIdx.x == 0) {
            while ((int)(ld_acq(&g_bar_gen) - gen) < 0) {}
        }
    }
    __syncthreads();
}

// ---------------- mma.sync / ldmatrix / cp.async macros -------------------------
#define LDSM4(r, addr) \
    asm volatile("ldmatrix.sync.aligned.m8n8.x4.shared.b16 {%0,%1,%2,%3}, [%4];" \
                 : "=r"((r)[0]), "=r"((r)[1]), "=r"((r)[2]), "=r"((r)[3]) \
                 : "r"(addr))
#define MMA16816(c, a, b0v, b1v) \
    asm volatile("mma.sync.aligned.m16n8k16.row.col.f32.bf16.bf16.f32 " \
                 "{%0,%1,%2,%3}, {%4,%5,%6,%7}, {%8,%9}, {%0,%1,%2,%3};" \
                 : "+f"((c)[0]), "+f"((c)[1]), "+f"((c)[2]), "+f"((c)[3]) \
                 : "r"((a)[0]), "r"((a)[1]), "r"((a)[2]), "r"((a)[3]), \
                   "r"(b0v), "r"(b1v))
__device__ __forceinline__ void cp16(uint32_t dst, const void* src) {
    asm volatile("cp.async.cg.shared.global [%0], [%1], 16;"
                 :: "r"(dst), "l"(src));
}
#define CP_COMMIT() asm volatile("cp.async.commit_group;" ::: "memory")
#define CP_WAIT(n) asm volatile("cp.async.wait_group %0;" :: "n"(n) : "memory")
__device__ __forceinline__ void sst16(uint32_t addr, unsigned short v) {
    asm volatile("st.shared.b16 [%0], %1;" :: "r"(addr), "h"(v));
}

// ---------------- 1. embedding gather + compensated layout ---------------------
__device__ __forceinline__ uint32_t packbf2(float a, float b) {
    __nv_bfloat162 t = __floats2bfloat162_rn(a, b);
    return *(uint32_t*)&t;
}
__global__ void embed_split_kernel(const int* __restrict__ tokens,
                                   const float* __restrict__ embedding) {
    int idx = blockIdx.x * blockDim.x + threadIdx.x;  // over SB * 64 (8 elems each)
    int e8 = idx & 63;
    int sb = idx >> 6;
    int tok = tokens[sb];
    const float4* src = (const float4*)(embedding + (size_t)tok * Ex + e8 * 8);
    float4 v0 = src[0], v1 = src[1];
    float hv[8], lo[8];
    float in[8] = {v0.x, v0.y, v0.z, v0.w, v1.x, v1.y, v1.z, v1.w};
#pragma unroll
    for (int i = 0; i < 8; ++i) {
        hv[i] = __bfloat162float(__float2bfloat16_rn(in[i]));
        lo[i] = in[i] - hv[i];
    }
    uint4 ph, pl;
    ph.x = packbf2(in[0], in[1]); ph.y = packbf2(in[2], in[3]);
    ph.z = packbf2(in[4], in[5]); ph.w = packbf2(in[6], in[7]);
    pl.x = packbf2(lo[0], lo[1]); pl.y = packbf2(lo[2], lo[3]);
    pl.z = packbf2(lo[4], lo[5]); pl.w = packbf2(lo[6], lo[7]);
    size_t off = (size_t)sb * AX + e8 * 8;
    *(uint4*)(g_ax + off) = ph;
    *(uint4*)(g_ax + off + 512) = pl;
}

// ---------------- 1b. W transpose + compensated layout --------------------------
__global__ void wsplit_kernel(const float* __restrict__ W, int which) {
    __shared__ float tile[32][33];
    __nv_bfloat16* dst = which ? g_bxb : g_bxf;
    const int kb = blockIdx.x;  // 16
    const int nb = blockIdx.y;  // 96
    const int t = threadIdx.x;
    const int c = t & 31;
    const int r0 = t >> 5;  // 0..7
#pragma unroll
    for (int q = 0; q < 4; ++q) {
        int r = r0 + 8 * q;
        tile[r][c] = W[(size_t)(kb * 32 + r) * G4x + nb * 32 + c];
    }
    __syncthreads();
#pragma unroll
    for (int q = 0; q < 4; ++q) {
        int i = r0 + 8 * q;            // n within tile
        float v = tile[c][i];          // W[kb*32+c][nb*32+i]
        __nv_bfloat16 hb = __float2bfloat16_rn(v);
        float hvf = __bfloat162float(hb);
        size_t off = (size_t)(nb * 32 + i) * KX + kb * 32 + c;
        dst[off] = hb;
        dst[off + 512] = hb;
        dst[off + 1024] = __float2bfloat16_rn(v - hvf);
    }
}

// ---------------- 2. warp-MMA input GEMM (uniform bf16, K=1536, 3-stage) --------
// 128-thread CTAs, tile 64m x 128n, BK=64, 3 CTAs/SM co-resident. (measured best)
#define TCW_STAGE 24576                 // A 8KB + B 16KB
#define TCW_SMEM (3 * TCW_STAGE)        // 72 KB

__device__ __forceinline__ void load_tileA64(const __nv_bfloat16* __restrict__ g,
                                             uint32_t sbase, int blk, int t) {
    int aoff = (blk < 16 ? blk : blk - 16) * 128;  // byte offset in 2048B row
#pragma unroll
    for (int q = 0; q < 4; ++q) {
        int idx = t + 128 * q;         // < 512 : 64 rows x 8 chunks
        int r = idx >> 3, c = idx & 7;
        const char* src = (const char*)g + (size_t)r * (AX * 2) + aoff + c * 16;
        uint32_t dst = sbase + r * 128 + ((c ^ (r & 7)) << 4);
        cp16(dst, src);
    }
}
__device__ __forceinline__ void load_tileB128(const __nv_bfloat16* __restrict__ g,
                                              uint32_t sbase, int blk, int t) {
#pragma unroll
    for (int q = 0; q < 8; ++q) {
        int idx = t + 128 * q;         // < 1024 : 128 rows x 8 chunks
        int r = idx >> 3, c = idx & 7;
        const char* src = (const char*)g + (size_t)r * (KX * 2) + blk * 128 + c * 16;
        uint32_t dst = sbase + r * 128 + ((c ^ (r & 7)) << 4);
        cp16(dst, src);
    }
}

__global__ __launch_bounds__(128, 2)
void tcw_gemm(const float* __restrict__ bias, int which) {
    extern __shared__ char smraw[];
    uint32_t smb = smem_u32(smraw);
    const int t = threadIdx.x;
    const int l = t & 31;
    const int wid = t >> 5;            // 0..3
    const int nblk = blockIdx.x;       // 24
    const int mblk = blockIdx.y;       // 512 (rows of 64)

    const __nv_bfloat16* Ag = g_ax + (size_t)mblk * 64 * AX;
    const __nv_bfloat16* Bg = (which ? g_bxb : g_bxf) + (size_t)nblk * 128 * KX;
    float* out = which ? g_gb : g_xf;

    float acc[2][8][4];
#pragma unroll
    for (int i = 0; i < 2; ++i)
#pragma unroll
        for (int j = 0; j < 8; ++j)
#pragma unroll
            for (int q = 0; q < 4; ++q) acc[i][j][q] = 0.0f;

    const int warp_m0 = (wid & 1) * 32;
    const int warp_n0 = (wid >> 1) * 64;
    const int ar = warp_m0 + (l & 15);
    const int ac_hi = l >> 4;
    const int br = warp_n0 + (l & 7) + ((l >> 4) << 3);
    const int bc_hi = (l >> 3) & 1;

    // prologue: stages 0,1
#pragma unroll
    for (int p = 0; p < 2; ++p) {
        uint32_t b0 = smb + p * TCW_STAGE;
        load_tileA64(Ag, b0, p, t);
        load_tileB128(Bg, b0 + 8192, p, t);
        CP_COMMIT();
    }

    int st_r = 0, st_w = 2;
    for (int blk = 0; blk < 24; ++blk) {
        if (blk < 22) {
            uint32_t nb = smb + st_w * TCW_STAGE;
            load_tileA64(Ag, nb, blk + 2, t);
            load_tileB128(Bg, nb + 8192, blk + 2, t);
            CP_COMMIT();
            st_w = (st_w == 2) ? 0 : st_w + 1;
        }
        if (blk <= 21) CP_WAIT(2);
        else if (blk == 22) CP_WAIT(1);
        else CP_WAIT(0);
        __syncthreads();

        uint32_t AB = smb + st_r * TCW_STAGE;
        uint32_t BB = AB + 8192;
#pragma unroll
        for (int ks = 0; ks < 4; ++ks) {
            uint32_t a_r[2][4];
#pragma unroll
            for (int mt = 0; mt < 2; ++mt) {
                int r = ar + mt * 16;
                int c = ks * 2 + ac_hi;
                LDSM4(a_r[mt], AB + r * 128 + ((c ^ (r & 7)) << 4));
            }
            uint32_t b_r[4][4];
#pragma unroll
            for (int np = 0; np < 4; ++np) {
                int r = br + np * 16;
                int c = ks * 2 + bc_hi;
                LDSM4(b_r[np], BB + r * 128 + ((c ^ (r & 7)) << 4));
            }
#pragma unroll
            for (int mt = 0; mt < 2; ++mt)
#pragma unroll
                for (int np = 0; np < 4; ++np)
#pragma unroll
                    for (int hf = 0; hf < 2; ++hf)
                        MMA16816(acc[mt][np * 2 + hf], a_r[mt],
                                 b_r[np][hf * 2], b_r[np][hf * 2 + 1]);
        }
        __syncthreads();
        st_r = (st_r == 2) ? 0 : st_r + 1;
    }

    const int row0 = mblk * 64 + warp_m0 + (l >> 2);
    const int col0 = nblk * 128 + warp_n0 + (l & 3) * 2;
#pragma unroll
    for (int mt = 0; mt < 2; ++mt) {
#pragma unroll
        for (int nt = 0; nt < 8; ++nt) {
            int rr = row0 + mt * 16;
            int cc = col0 + nt * 8;
            float2 bv = *(const float2*)(bias + cc);
            float2 o0, o1;
            o0.x = acc[mt][nt][0] + bv.x;
            o0.y = acc[mt][nt][1] + bv.y;
            o1.x = acc[mt][nt][2] + bv.x;
            o1.y = acc[mt][nt][3] + bv.y;
            *(float2*)(out + (size_t)rr * G4x + cc) = o0;
            *(float2*)(out + (size_t)(rr + 8) * G4x + cc) = o1;
        }
    }
}

// ---------------- 3. persistent forward recurrence (dedup smem, occ 1) ----------
// CTA (nblk = bid%24, kc = bid/24). smem 96 KB, 1 CTA/SM, FULL registers:
//   Hsm [64 b][32 ch]  = 32 KB : chunks 0-15 = h_hi, 16-31 = h_lo
//   Wsm [128 n][32 ch] = 64 KB : chunks 0-15 = W_hi, 16-31 = W_lo
// Per k16-chunk: load Ah/Al/Bh/Bl fragments once (8 LDSM), issue all three
// compensation products (Ah*Bh + Al*Bh + Ah*Bl) from registers.
#define FWD_SMEM 98304
#define HP2 512

__device__ __forceinline__ uint32_t swadr2(uint32_t base, int r, int chunk) {
    return base + r * HP2 + ((chunk ^ (r & 7)) << 4);
}

__global__ __launch_bounds__(256, 1)
void fwd_persistent(const float* __restrict__ Wh, const float* __restrict__ bh) {
    extern __shared__ char smraw[];
    const uint32_t HB = smem_u32(smraw);
    const uint32_t WB = HB + 32768;

    const int t = threadIdx.x;
    const int l = t & 31;
    const int wid = t >> 5;
    const int bid = blockIdx.x;
    const int nblk = bid % 24;
    const int kc = bid / 24;
    unsigned int gen = ld_acq(&g_bar_gen);  // monotonic seed

    // zero hidden hi/lo
    for (int i = bid * 256 + t; i < NUNIT; i += NTHR) {
        __stcg(&g_hhi[i], 0u);
        __stcg(&g_hlo[i], 0u);
    }

    // one-time W tile split: Wsm[n][hi|lo] from Wh[kc*128+k][nblk*128+n]
    for (int idx = t; idx < 128 * 128; idx += 256) {
        int n = idx & 127;
        int k = idx >> 7;
        float v = Wh[(size_t)(kc * 128 + k) * G4x + nblk * 128 + n];
        __nv_bfloat16 hb = __float2bfloat16_rn(v);
        float hvf = __bfloat162float(hb);
        __nv_bfloat16 lb = __float2bfloat16_rn(v - hvf);
        int ch = k >> 3, in8 = (k & 7) << 1;
        sst16(swadr2(WB, n, ch) + in8, *(unsigned short*)&hb);
        sst16(swadr2(WB, n, 16 + ch) + in8, *(unsigned short*)&lb);
    }

    // gates: balanced contiguous unit ranges, 170-171 units per CTA
    const int ustart = (512 * bid) / 3;
    const int uend = (512 * (bid + 1)) / 3;
    const int u = ustart + t;
    const bool act = (t < uend - ustart);
    int gb = 0, gj = 0;
    float2 bh2[4];
    float c0 = 0.0f, c1 = 0.0f;
    if (act) {
        gb = u / 384;
        gj = (u - gb * 384) * 2;
#pragma unroll
        for (int gi = 0; gi < 4; ++gi)
            bh2[gi] = *(const float2*)(bh + gj + gi * Hx);
    }

    // mma addressing: 8 warps = 2 m-groups x 4 n-groups
    const int mg = wid >> 2;
    const int ng = wid & 3;
    const int ar_ = mg * 32 + (l & 15);
    const int ac_hi = l >> 4;
    const int br_ = ng * 32 + (l & 7) + ((l >> 4) << 3);
    const int bc_hi = (l >> 3) & 1;

    // prefetch xf for s=0 (independent of recurrence state)
    float2 xf2[4];
    if (act) {
        const float* xfp = g_xf + (size_t)gb * G4x + gj;
#pragma unroll
        for (int gi = 0; gi < 4; ++gi)
            xf2[gi] = __ldcs((const float2*)(xfp + gi * Hx));
    }

    gsync(gen);  // W tile + zeroed h visible everywhere

    for (int s = 0; s < Sx; ++s) {
        // cp.async h tiles: [hi | lo] from g_hhi/g_hlo (bf16 pairs), 32 KB
#pragma unroll
        for (int q = 0; q < 8; ++q) {
            int idx2 = t + 256 * (q & 3);  // < 1024
            int region = q >> 2;           // 0:hi 1:lo
            int b = idx2 >> 4, c16 = idx2 & 15;
            const char* src =
                (const char*)(region ? g_hlo : g_hhi) + b * 1536 +
                kc * 256 + c16 * 16;
            cp16(swadr2(HB, b, region * 16 + c16), src);
        }
        CP_COMMIT();
        CP_WAIT(0);
        __syncthreads();

        // mma GEMM: per k16-chunk load 4 fragment sets, 3 products each
        float acc[2][4][4];
#pragma unroll
        for (int i = 0; i < 2; ++i)
#pragma unroll
            for (int j = 0; j < 4; ++j)
#pragma unroll
                for (int q = 0; q < 4; ++q) acc[i][j][q] = 0.0f;

#pragma unroll
        for (int c8 = 0; c8 < 8; ++c8) {
            uint32_t aH[2][4], aL[2][4];
#pragma unroll
            for (int mt = 0; mt < 2; ++mt) {
                int r = ar_ + mt * 16;
                int cH = c8 * 2 + ac_hi;
                int cL = (8 + c8) * 2 + ac_hi;
                LDSM4(aH[mt], HB + r * HP2 + ((cH ^ (r & 7)) << 4));
                LDSM4(aL[mt], HB + r * HP2 + ((cL ^ (r & 7)) << 4));
            }
            uint32_t bH[2][4], bL[2][4];
#pragma unroll
            for (int np = 0; np < 2; ++np) {
                int r = br_ + np * 16;
                int cH = c8 * 2 + bc_hi;
                int cL = (8 + c8) * 2 + bc_hi;
                LDSM4(bH[np], WB + r * HP2 + ((cH ^ (r & 7)) << 4));
                LDSM4(bL[np], WB + r * HP2 + ((cL ^ (r & 7)) << 4));
            }
#pragma unroll
            for (int mt = 0; mt < 2; ++mt) {
#pragma unroll
                for (int np = 0; np < 2; ++np) {
#pragma unroll
                    for (int hf = 0; hf < 2; ++hf) {
                        int nt = np * 2 + hf;
                        MMA16816(acc[mt][nt], aH[mt], bH[np][hf * 2],
                                 bH[np][hf * 2 + 1]);
                        MMA16816(acc[mt][nt], aL[mt], bH[np][hf * 2],
                                 bH[np][hf * 2 + 1]);
                        MMA16816(acc[mt][nt], aH[mt], bL[np][hf * 2],
                                 bL[np][hf * 2 + 1]);
                    }
                }
            }
        }

        // epilogue -> g_part[kc][b][n] (L2-coherent)
        {
            const int row0 = mg * 32 + (l >> 2);
            const int col0 = nblk * 128 + ng * 32 + (l & 3) * 2;
#pragma unroll
            for (int mt = 0; mt < 2; ++mt) {
#pragma unroll
                for (int nt = 0; nt < 4; ++nt) {
                    int b = row0 + mt * 16;
                    int n = col0 + nt * 8;
                    float2 v0 = {acc[mt][nt][0], acc[mt][nt][1]};
                    float2 v1 = {acc[mt][nt][2], acc[mt][nt][3]};
                    __stcg((float2*)(g_part + ((size_t)(kc * Bx + b)) * G4x + n), v0);
                    __stcg((float2*)(g_part + ((size_t)(kc * Bx + b + 8)) * G4x + n),
                           v1);
                }
            }
        }
        gsync(gen);

        // gates (one float2 unit per active thread; MUFU transcendentals)
        if (act) {
            float g0[4], g1[4];
#pragma unroll
            for (int gi = 0; gi < 4; ++gi) {
                float v0 = xf2[gi].x + bh2[gi].x;
                float v1 = xf2[gi].y + bh2[gi].y;
                const float* pp = g_part + (size_t)gb * G4x + gj + gi * Hx;
#pragma unroll
                for (int kcc = 0; kcc < 6; ++kcc) {
                    float2 pv = __ldcg((const float2*)(pp + (size_t)kcc *
                                                       (Bx * G4x)));
                    v0 += pv.x;
                    v1 += pv.y;
                }
                g0[gi] = v0;
                g1[gi] = v1;
            }
            float r0 = fsigm(g0[0]), f0 = fsigm(g0[1]);
            float t0 = ftanh(g0[2]), o0 = fsigm(g0[3]);
            float r1 = fsigm(g1[0]), f1 = fsigm(g1[1]);
            float t1 = ftanh(g1[2]), o1 = fsigm(g1[3]);
            c0 = f0 * c0 + r0 * t0;
            c1 = f1 * c1 + r1 * t1;
            float h0 = o0 * ftanh(c0);
            float h1 = o1 * ftanh(c1);
            float2 h2 = {h0, h1};
            *(float2*)(g_hsf + (size_t)s * (Bx * Hx) + gb * Hx + gj) = h2;
            float hr0 = __bfloat162float(__float2bfloat16_rn(h0));
            float hr1 = __bfloat162float(__float2bfloat16_rn(h1));
            __stcg(&g_hhi[u], packbf2(h0, h1));
            __stcg(&g_hlo[u], packbf2(h0 - hr0, h1 - hr1));
            // prefetch xf for next step (independent of the barrier below)
            if (s + 1 < Sx) {
                const float* xfp = g_xf + ((size_t)(s + 1) * Bx + gb) * G4x + gj;
#pragma unroll
                for (int gi = 0; gi < 4; ++gi)
                    xf2[gi] = __ldcs((const float2*)(xfp + gi * Hx));
            }
        }
        gsync(gen);
    }
}

// ---------------- 4. one-shot hidden GEMM for hT @ Wh_b (split-K partials) ----
__global__ __launch_bounds__(256, 2)
void step_gemm_kernel(const float* __restrict__ Wh) {
    __shared__ float hsT[16][68];
    __shared__ float Wsm[16][128];
    const float* hsrc = g_hsf + (size_t)(Sx - 1) * Bx * Hx;  // hT = hsf[511]
    const int t = threadIdx.x;
    const int nblk = blockIdx.x;  // 24
    const int kc = blockIdx.y;    // 6
    const float* Wb = Wh + nblk * 128;

    unsigned long long acc[4][4];
#pragma unroll
    for (int i = 0; i < 4; ++i)
#pragma unroll
        for (int j = 0; j < 4; ++j) acc[i][j] = 0ull;

    const int la_b = t >> 2;
    const int la_k = (t & 3) * 4;
    const int lb_k = t >> 5;
    const int lb_n = (t & 31) * 4;
    const int b0 = (t >> 4) * 4;
    const int n0 = (t & 15) * 8;

    for (int kt = 0; kt < 8; ++kt) {
        int k0 = kc * 128 + kt * 16;
        float4 va = *(const float4*)(hsrc + la_b * Hx + k0 + la_k);
        float4 vb0 = *(const float4*)(Wb + (size_t)(k0 + lb_k) * G4x + lb_n);
        float4 vb1 = *(const float4*)(Wb + (size_t)(k0 + lb_k + 8) * G4x + lb_n);
        hsT[la_k + 0][la_b] = va.x; hsT[la_k + 1][la_b] = va.y;
        hsT[la_k + 2][la_b] = va.z; hsT[la_k + 3][la_b] = va.w;
        *(float4*)(&Wsm[lb_k][lb_n]) = vb0;
        *(float4*)(&Wsm[lb_k + 8][lb_n]) = vb1;
        __syncthreads();
#pragma unroll
        for (int k = 0; k < 16; ++k) {
            float a[4];
            *(float4*)a = *(const float4*)(&hsT[k][b0]);
            ulonglong2 b01 = *(const ulonglong2*)(&Wsm[k][n0]);
            ulonglong2 b23 = *(const ulonglong2*)(&Wsm[k][n0 + 4]);
            unsigned long long bb0 = b01.x, bb1 = b01.y, bb2 = b23.x, bb3 = b23.y;
#pragma unroll
            for (int i = 0; i < 4; ++i) {
                unsigned long long a2 = pack2(a[i]);
                fma2(acc[i][0], a2, bb0);
                fma2(acc[i][1], a2, bb1);
                fma2(acc[i][2], a2, bb2);
                fma2(acc[i][3], a2, bb3);
            }
        }
        __syncthreads();
    }
#pragma unroll
    for (int i = 0; i < 4; ++i) {
#pragma unroll
        for (int j = 0; j < 4; ++j) {
            float2 v = unpack2(acc[i][j]);
            int gn = nblk * 128 + n0 + j * 2;
            *(float2*)(g_part + ((size_t)(kc * Bx + b0 + i)) * G4x + gn) = v;
        }
    }
}

// ---------------- 5. backward (constant-hT) scan --------------------------------
__global__ void bscan_kernel(const float* __restrict__ bh) {
    int idx = blockIdx.x * 256 + threadIdx.x;  // < 49152
    int b = idx / Hx;
    int j = idx - b * Hx;
    float hw[4];
#pragma unroll
    for (int gi = 0; gi < 4; ++gi) {
        int col = j + gi * Hx;
        float v = bh[col];
#pragma unroll
        for (int kc = 0; kc < 6; ++kc)
            v += g_part[((size_t)(kc * Bx + b)) * G4x + col];
        hw[gi] = v;
    }
    float c2 = 0.f;
#pragma unroll 4
    for (int s = Sx - 1; s >= 0; --s) {
        const float* gbp = g_gb + ((size_t)s * Bx + b) * G4x + j;
        float r = fsigm(__ldcs(gbp) + hw[0]);
        float f = fsigm(__ldcs(gbp + Hx) + hw[1]);
        float gg = ftanh(__ldcs(gbp + 2 * Hx) + hw[2]);
        float o = fsigm(__ldcs(gbp + 3 * Hx) + hw[3]);
        c2 = f * c2 + r * gg;
        g_hsb[(size_t)s * (Bx * Hx) + idx] = o * ftanh(c2);
    }
}

// ---------------- 6. output GEMM + pad bias -------------------------------------
__global__ __launch_bounds__(256, 2)
void out_kernel(const float* __restrict__ Wout, const float* __restrict__ bout,
                const int* __restrict__ tokens, float* __restrict__ out) {
    __shared__ float As[64][65];
    __shared__ float Wsm[64][33];
    const int t = threadIdx.x;
    const int rb = blockIdx.x;  // 512
    const int l = t & 31;
    const int rg = t >> 5;  // 0..7
    float acc[8];
#pragma unroll
    for (int i = 0; i < 8; ++i) acc[i] = 0.f;

    for (int kt = 0; kt < 24; ++kt) {
        int k0 = kt * 64;
        const float* src_base = (k0 < Hx) ? g_hsf : g_hsb;
        int koff = (k0 < Hx) ? k0 : (k0 - Hx);
#pragma unroll
        for (int q = 0; q < 4; ++q) {
            int i = t + 256 * q;
            int row = i >> 4;
            int kq = (i & 15) * 4;
            const float* src =
                src_base + ((size_t)(rb * 64 + row)) * Hx + koff + kq;
            float4 v = *(const float4*)src;
            As[row][kq] = v.x; As[row][kq + 1] = v.y;
            As[row][kq + 2] = v.z; As[row][kq + 3] = v.w;
        }
#pragma unroll
        for (int q = 0; q < 2; ++q) {
            int i = t + 256 * q;
            int k = i >> 3;
            int lq = (i & 7) * 4;
            float4 v = *(const float4*)(Wout + (size_t)(k0 + k) * 32 + lq);
            Wsm[k][lq] = v.x; Wsm[k][lq + 1] = v.y;
            Wsm[k][lq + 2] = v.z; Wsm[k][lq + 3] = v.w;
        }
        __syncthreads();
#pragma unroll 8
        for (int k = 0; k < 64; ++k) {
            float w = Wsm[k][l];
#pragma unroll
            for (int i = 0; i < 8; ++i) acc[i] += As[rg * 8 + i][k] * w;
        }
        __syncthreads();
    }
#pragma unroll
    for (int i = 0; i < 8; ++i) {
        int row = rb * 64 + rg * 8 + i;
        float v = acc[i] + bout[l];
        if (l == 0 && tokens[row] == 1) v += 10000.0f;
        out[(size_t)row * 32 + l] = v;
    }
}

// ---------------- launch ---------------------------------------------------------
extern "C" void kernel_launch(void* const* d_in, const int* in_sizes, int n_in,
                              void* d_out, int out_size) {
    (void)in_sizes; (void)n_in; (void)out_size;
    const int* tokens = (const int*)d_in[0];
    const float* embedding = (const float*)d_in[2];
    const float* Wi_f = (const float*)d_in[3];
    const float* bi_f = (const float*)d_in[4];
    const float* Wh_f = (const float*)d_in[5];
    const float* bh_f = (const float*)d_in[6];
    const float* Wi_b = (const float*)d_in[7];
    const float* bi_b = (const float*)d_in[8];
    const float* Wh_b = (const float*)d_in[9];
    const float* bh_b = (const float*)d_in[10];
    const float* Wout = (const float*)d_in[11];
    const float* bout = (const float*)d_in[12];
    float* out = (float*)d_out;

    cudaFuncSetAttribute(fwd_persistent,
                         cudaFuncAttributeMaxDynamicSharedMemorySize, FWD_SMEM);
    cudaFuncSetAttribute(tcw_gemm,
                         cudaFuncAttributeMaxDynamicSharedMemorySize, TCW_SMEM);

    // 1. gather embeddings into compensated bf16 layout [Ah|Al]
    embed_split_kernel<<<SBx * 64 / 256, 256>>>(tokens, embedding);
    // 2. input projections via single uniform bf16 MMA GEMM (K=1536, 3-stage)
    wsplit_kernel<<<dim3(16, 96), 256>>>(Wi_f, 0);
    wsplit_kernel<<<dim3(16, 96), 256>>>(Wi_b, 1);
    tcw_gemm<<<dim3(24, 512), 128, TCW_SMEM>>>(bi_f, 0);
    tcw_gemm<<<dim3(24, 512), 128, TCW_SMEM>>>(bi_b, 1);
    // 3. forward LSTM recurrence (dedup smem, occ 1, fragment-held 3-pass)
    fwd_persistent<<<NCTA, 256, FWD_SMEM>>>(Wh_f, bh_f);
    // 4. hT @ Wh_b partials
    step_gemm_kernel<<<dim3(24, 6), 256>>>(Wh_b);
    // 5. backward scan
    bscan_kernel<<<192, 256>>>(bh_b);
    // 6. output projection + pad bias
    out_kernel<<<512, 256>>>(Wout, bout, tokens, out);
}